// round 2
// baseline (speedup 1.0000x reference)
#include <cuda_runtime.h>

#define N_NODES 100000
#define N_EDGES 1600000
#define HIDDEN 128
#define NUM_CLASSES 10
#define NUM_LAYERS 4
#define NUM_GRAPHS 200
#define BN_EPS 1e-5f

// ---------------- scratch (static device arrays: no allocations) ----------------
__device__ float d_h[(size_t)N_NODES * HIDDEN];      // node state (51.2 MB)
__device__ float d_m[(size_t)N_NODES * HIDDEN];      // messages / fc1 out
__device__ float d_agg[(size_t)N_NODES * HIDDEN];    // aggregated messages
__device__ float d_G[(size_t)N_NODES * 6 * HIDDEN];  // [gi(384) | gh(384)] (307 MB)
__device__ int d_src[N_EDGES];
__device__ int d_dst[N_EDGES];
__device__ int d_deg[N_NODES];
__device__ int d_rowptr[N_NODES + 1];
__device__ int d_cursor[N_NODES];
__device__ int d_colidx[N_EDGES];
__device__ float d_sum[HIDDEN], d_sumsq[HIDDEN], d_mean[HIDDEN], d_rstd[HIDDEN];
__device__ float d_pool[NUM_GRAPHS * HIDDEN];
__device__ int d_cnt[NUM_GRAPHS];

// ---------------- small helpers ----------------
__device__ __forceinline__ float sigm_f(float x) {
    return __fdividef(1.f, 1.f + __expf(-x));
}
__device__ __forceinline__ float tanh_f(float x) {
    return 1.f - __fdividef(2.f, __expf(2.f * x) + 1.f);
}

// ---------------- init / setup kernels ----------------
__global__ void k_init() {
    int i = blockIdx.x * blockDim.x + threadIdx.x;
    if (i < N_NODES) d_deg[i] = 0;
    if (i < NUM_GRAPHS * HIDDEN) d_pool[i] = 0.f;
    if (i < NUM_GRAPHS) d_cnt[i] = 0;
    if (i < HIDDEN) { d_sum[i] = 0.f; d_sumsq[i] = 0.f; }
}

__global__ void k_copy_x(const float* __restrict__ x) {
    int i = blockIdx.x * blockDim.x + threadIdx.x;  // over float4, 3.2M
    ((float4*)d_h)[i] = ((const float4*)x)[i];
}

__global__ void k_edges(const int* __restrict__ e) {
    int i = blockIdx.x * blockDim.x + threadIdx.x;  // < N_EDGES
    int s = e[i];
    int d = e[N_EDGES + i];
    d_src[i] = s;
    d_dst[i] = d;
    atomicAdd(&d_deg[d], 1);
}

__global__ void k_batch_hist(const int* __restrict__ batch) {
    int i = blockIdx.x * blockDim.x + threadIdx.x;
    if (i < N_NODES) atomicAdd(&d_cnt[batch[i]], 1);
}

__global__ void k_scan() {
    __shared__ int s[1024];
    __shared__ int carry;
    int t = threadIdx.x;
    if (t == 0) carry = 0;
    __syncthreads();
    for (int base = 0; base < N_NODES; base += 1024) {
        int idx = base + t;
        int v = (idx < N_NODES) ? d_deg[idx] : 0;
        s[t] = v;
        __syncthreads();
        for (int off = 1; off < 1024; off <<= 1) {
            int tmp = (t >= off) ? s[t - off] : 0;
            __syncthreads();
            s[t] += tmp;
            __syncthreads();
        }
        if (idx < N_NODES) {
            int ex = carry + s[t] - v;
            d_rowptr[idx] = ex;
            d_cursor[idx] = ex;
        }
        __syncthreads();
        if (t == 0) carry += s[1023];
        __syncthreads();
    }
    if (t == 0) d_rowptr[N_NODES] = carry;
}

__global__ void k_csr_fill() {
    int i = blockIdx.x * blockDim.x + threadIdx.x;  // < N_EDGES
    int pos = atomicAdd(&d_cursor[d_dst[i]], 1);
    d_colidx[pos] = d_src[i];
}

// ---------------- fp32 tiled GEMM: C[row, ccol0+0..127] over K=128 ----------------
template <bool TRANSB, bool HASBIAS>
__device__ __forceinline__ void gemm_tile(
    const float* __restrict__ A, const float* __restrict__ B,
    const float* __restrict__ bias,
    float* __restrict__ C, int ldc, int ccol0, int bcol0)
{
    __shared__ float As[16][128];
    __shared__ float Bs[16][128];
    const int tid = threadIdx.x;       // 256
    const int tx = tid & 15, ty = tid >> 4;
    const int row0 = blockIdx.x * 128;

    float acc[8][8];
#pragma unroll
    for (int i = 0; i < 8; i++)
#pragma unroll
        for (int j = 0; j < 8; j++) acc[i][j] = 0.f;

    for (int k0 = 0; k0 < 128; k0 += 16) {
#pragma unroll
        for (int q = tid; q < 512; q += 256) {
            int r = q >> 2, kq = (q & 3) << 2;
            float4 v = make_float4(0.f, 0.f, 0.f, 0.f);
            int gr = row0 + r;
            if (gr < N_NODES) v = *(const float4*)(A + (size_t)gr * HIDDEN + k0 + kq);
            As[kq + 0][r] = v.x; As[kq + 1][r] = v.y;
            As[kq + 2][r] = v.z; As[kq + 3][r] = v.w;
        }
        if (!TRANSB) {
#pragma unroll
            for (int q = tid; q < 512; q += 256) {
                int kk = q >> 5, nq = (q & 31) << 2;
                *(float4*)&Bs[kk][nq] = *(const float4*)(B + (size_t)(k0 + kk) * 128 + nq);
            }
        } else {
#pragma unroll
            for (int q = tid; q < 512; q += 256) {
                int n = q >> 2, kq = (q & 3) << 2;
                float4 v = *(const float4*)(B + (size_t)(bcol0 + n) * 128 + k0 + kq);
                Bs[kq + 0][n] = v.x; Bs[kq + 1][n] = v.y;
                Bs[kq + 2][n] = v.z; Bs[kq + 3][n] = v.w;
            }
        }
        __syncthreads();
#pragma unroll
        for (int kk = 0; kk < 16; kk++) {
            float4 a0 = *(float4*)&As[kk][ty * 8];
            float4 a1 = *(float4*)&As[kk][ty * 8 + 4];
            float4 b0 = *(float4*)&Bs[kk][tx * 8];
            float4 b1 = *(float4*)&Bs[kk][tx * 8 + 4];
            float a[8] = {a0.x, a0.y, a0.z, a0.w, a1.x, a1.y, a1.z, a1.w};
            float b[8] = {b0.x, b0.y, b0.z, b0.w, b1.x, b1.y, b1.z, b1.w};
#pragma unroll
            for (int i = 0; i < 8; i++)
#pragma unroll
                for (int j = 0; j < 8; j++) acc[i][j] = fmaf(a[i], b[j], acc[i][j]);
        }
        __syncthreads();
    }

    float bb[8];
#pragma unroll
    for (int j = 0; j < 8; j++) bb[j] = HASBIAS ? bias[tx * 8 + j] : 0.f;

#pragma unroll
    for (int i = 0; i < 8; i++) {
        int gr = row0 + ty * 8 + i;
        if (gr < N_NODES) {
            float* crow = C + (size_t)gr * ldc + ccol0 + tx * 8;
            float4 v0, v1;
            v0.x = acc[i][0] + bb[0]; v0.y = acc[i][1] + bb[1];
            v0.z = acc[i][2] + bb[2]; v0.w = acc[i][3] + bb[3];
            v1.x = acc[i][4] + bb[4]; v1.y = acc[i][5] + bb[5];
            v1.z = acc[i][6] + bb[6]; v1.w = acc[i][7] + bb[7];
            *(float4*)crow = v0;
            *(float4*)(crow + 4) = v1;
        }
    }
}

__global__ void __launch_bounds__(256) k_gemm_msg(const float* __restrict__ W) {
    gemm_tile<false, false>(d_h, W, nullptr, d_m, HIDDEN, 0, 0);
}

__global__ void __launch_bounds__(256) k_gemm_gru(
    const float* __restrict__ wih, const float* __restrict__ whh,
    const float* __restrict__ bih, const float* __restrict__ bhh)
{
    int p = blockIdx.y;  // 0..5 : 0-2 -> gi tiles, 3-5 -> gh tiles
    const float* A = (p < 3) ? d_agg : d_h;
    const float* B = (p < 3) ? wih : whh;
    int bcol0 = (p % 3) * 128;
    const float* bias = ((p < 3) ? bih : bhh) + bcol0;
    gemm_tile<true, true>(A, B, bias, d_G, 6 * HIDDEN, p * 128, bcol0);
}

__global__ void __launch_bounds__(256) k_gemm_fc1(
    const float* __restrict__ w, const float* __restrict__ b) {
    gemm_tile<true, true>(d_h, w, b, d_m, HIDDEN, 0, 0);
}

// ---------------- CSR aggregate: one warp per destination node ----------------
__global__ void k_aggregate() {
    int warp = (blockIdx.x * blockDim.x + threadIdx.x) >> 5;
    int lane = threadIdx.x & 31;
    if (warp >= N_NODES) return;
    int beg = d_rowptr[warp], end = d_rowptr[warp + 1];
    float4 acc = make_float4(0.f, 0.f, 0.f, 0.f);
    for (int e = beg; e < end; e++) {
        int src = d_colidx[e];
        float4 v = *(const float4*)(d_m + (size_t)src * HIDDEN + lane * 4);
        acc.x += v.x; acc.y += v.y; acc.z += v.z; acc.w += v.w;
    }
    *(float4*)(d_agg + (size_t)warp * HIDDEN + lane * 4) = acc;
}

// ---------------- GRU elementwise update (in-place on d_h) ----------------
__global__ void k_gru_update() {
    int t = blockIdx.x * blockDim.x + threadIdx.x;  // over N_NODES*32 float4 cols
    int n = t >> 5, c4 = (t & 31) << 2;
    const float* g = d_G + (size_t)n * (6 * HIDDEN) + c4;
    float4 ir = *(const float4*)(g + 0 * HIDDEN);
    float4 iz = *(const float4*)(g + 1 * HIDDEN);
    float4 in_ = *(const float4*)(g + 2 * HIDDEN);
    float4 hr = *(const float4*)(g + 3 * HIDDEN);
    float4 hz = *(const float4*)(g + 4 * HIDDEN);
    float4 hn = *(const float4*)(g + 5 * HIDDEN);
    float* hp = d_h + (size_t)n * HIDDEN + c4;
    float4 h = *(float4*)hp;
    float4 o;
    {
        float r = sigm_f(ir.x + hr.x), z = sigm_f(iz.x + hz.x);
        float nn = tanh_f(in_.x + r * hn.x);
        o.x = (1.f - z) * nn + z * h.x;
    }
    {
        float r = sigm_f(ir.y + hr.y), z = sigm_f(iz.y + hz.y);
        float nn = tanh_f(in_.y + r * hn.y);
        o.y = (1.f - z) * nn + z * h.y;
    }
    {
        float r = sigm_f(ir.z + hr.z), z = sigm_f(iz.z + hz.z);
        float nn = tanh_f(in_.z + r * hn.z);
        o.z = (1.f - z) * nn + z * h.z;
    }
    {
        float r = sigm_f(ir.w + hr.w), z = sigm_f(iz.w + hz.w);
        float nn = tanh_f(in_.w + r * hn.w);
        o.w = (1.f - z) * nn + z * h.w;
    }
    *(float4*)hp = o;
}

// ---------------- batchnorm (training stats) + relu + mean pool ----------------
__global__ void k_bn_stats() {
    int c = threadIdx.x;                 // 128 threads, thread = column
    int n0 = blockIdx.x * 500;           // 200 blocks
    int n1 = n0 + 500;
    float s = 0.f, s2 = 0.f;
    for (int n = n0; n < n1; n++) {
        float v = d_m[(size_t)n * HIDDEN + c];
        s += v;
        s2 += v * v;
    }
    atomicAdd(&d_sum[c], s);
    atomicAdd(&d_sumsq[c], s2);
}

__global__ void k_bn_final() {
    int c = threadIdx.x;
    float mu = d_sum[c] / (float)N_NODES;
    float var = d_sumsq[c] / (float)N_NODES - mu * mu;
    d_mean[c] = mu;
    d_rstd[c] = rsqrtf(var + BN_EPS);
}

__global__ void k_pool(const int* __restrict__ batch,
                       const float* __restrict__ gamma,
                       const float* __restrict__ beta) {
    int c = threadIdx.x;  // 128 threads
    int n0 = blockIdx.x * 512;
    int n1 = n0 + 512;
    if (n1 > N_NODES) n1 = N_NODES;
    if (n0 >= N_NODES) return;
    float sc = gamma[c] * d_rstd[c];
    float mu = d_mean[c];
    float be = beta[c];
    float acc = 0.f;
    int cur = batch[n0];
    for (int n = n0; n < n1; n++) {
        int bb = batch[n];
        if (bb != cur) {
            atomicAdd(&d_pool[cur * HIDDEN + c], acc);
            acc = 0.f;
            cur = bb;
        }
        float v = (d_m[(size_t)n * HIDDEN + c] - mu) * sc + be;
        acc += fmaxf(v, 0.f);
    }
    atomicAdd(&d_pool[cur * HIDDEN + c], acc);
}

__global__ void k_final(const float* __restrict__ w2, const float* __restrict__ b2,
                        float* __restrict__ out) {
    __shared__ float sf[HIDDEN];
    __shared__ float lg[NUM_CLASSES];
    int g = blockIdx.x, t = threadIdx.x;
    float cnt = fmaxf((float)d_cnt[g], 1.f);
    sf[t] = d_pool[g * HIDDEN + t] / cnt;
    __syncthreads();
    if (t < NUM_CLASSES) {
        float s = b2[t];
        for (int k = 0; k < HIDDEN; k++) s += sf[k] * w2[t * HIDDEN + k];
        lg[t] = s;
    }
    __syncthreads();
    if (t == 0) {
        float mx = -1e30f;
        for (int c = 0; c < NUM_CLASSES; c++) mx = fmaxf(mx, lg[c]);
        float se = 0.f;
        for (int c = 0; c < NUM_CLASSES; c++) se += expf(lg[c] - mx);
        float lse = mx + logf(se);
        for (int c = 0; c < NUM_CLASSES; c++) out[g * NUM_CLASSES + c] = lg[c] - lse;
    }
}

// ---------------- launch ----------------
extern "C" void kernel_launch(void* const* d_in, const int* in_sizes, int n_in,
                              void* d_out, int out_size) {
    const float* x        = (const float*)d_in[0];
    const int*   ei       = (const int*)d_in[1];
    const int*   bat      = (const int*)d_in[2];
    const float* ggnn     = (const float*)d_in[3];
    const float* wih      = (const float*)d_in[4];
    const float* whh      = (const float*)d_in[5];
    const float* bih      = (const float*)d_in[6];
    const float* bhh      = (const float*)d_in[7];
    const float* fc1w     = (const float*)d_in[8];
    const float* fc1b     = (const float*)d_in[9];
    const float* gamma    = (const float*)d_in[10];
    const float* beta     = (const float*)d_in[11];
    const float* fc2w     = (const float*)d_in[12];
    const float* fc2b     = (const float*)d_in[13];
    float* out = (float*)d_out;

    k_init<<<(N_NODES + 255) / 256, 256>>>();
    k_copy_x<<<(N_NODES * HIDDEN / 4) / 256, 256>>>(x);
    k_edges<<<N_EDGES / 256, 256>>>(ei);
    k_batch_hist<<<(N_NODES + 255) / 256, 256>>>(bat);
    k_scan<<<1, 1024>>>();
    k_csr_fill<<<N_EDGES / 256, 256>>>();

    const int gemm_blocks = (N_NODES + 127) / 128;  // 782
    for (int l = 0; l < NUM_LAYERS; l++) {
        k_gemm_msg<<<gemm_blocks, 256>>>(ggnn + (size_t)l * HIDDEN * HIDDEN);
        k_aggregate<<<(N_NODES * 32) / 256, 256>>>();
        k_gemm_gru<<<dim3(gemm_blocks, 6), 256>>>(wih, whh, bih, bhh);
        k_gru_update<<<(N_NODES * 32) / 256, 256>>>();
    }

    k_gemm_fc1<<<gemm_blocks, 256>>>(fc1w, fc1b);
    k_bn_stats<<<200, 128>>>();
    k_bn_final<<<1, 128>>>();
    k_pool<<<(N_NODES + 511) / 512, 128>>>(bat, gamma, beta);
    k_final<<<NUM_GRAPHS, 128>>>(fc2w, fc2b, out);
}

// round 4
// speedup vs baseline: 1.7271x; 1.7271x over previous
#include <cuda_runtime.h>
#include <cstdint>

#define N_NODES 100000
#define N_EDGES 1600000
#define HIDDEN 128
#define NUM_CLASSES 10
#define NUM_LAYERS 4
#define NUM_GRAPHS 200
#define BN_EPS 1e-5f

// ---------------- scratch (static device arrays: no allocations) ----------------
__device__ float d_h[(size_t)N_NODES * HIDDEN];
__device__ float d_m[(size_t)N_NODES * HIDDEN];
__device__ float d_agg[(size_t)N_NODES * HIDDEN];
__device__ float d_G[(size_t)N_NODES * 6 * HIDDEN];
__device__ float d_Wt[HIDDEN * HIDDEN];
__device__ int d_src[N_EDGES];
__device__ int d_dst[N_EDGES];
__device__ int d_deg[N_NODES];
__device__ int d_rowptr[N_NODES + 1];
__device__ int d_cursor[N_NODES];
__device__ int d_colidx[N_EDGES];
__device__ float d_sum[HIDDEN], d_sumsq[HIDDEN], d_mean[HIDDEN], d_rstd[HIDDEN];
__device__ float d_pool[NUM_GRAPHS * HIDDEN];
__device__ int d_cnt[NUM_GRAPHS];

// ---------------- helpers ----------------
__device__ __forceinline__ float sigm_f(float x) {
    return __fdividef(1.f, 1.f + __expf(-x));
}
__device__ __forceinline__ float tanh_f(float x) {
    return 1.f - __fdividef(2.f, __expf(2.f * x) + 1.f);
}
__device__ __forceinline__ uint32_t f2tf32(float f) {
    uint32_t r;
    asm("cvt.rna.tf32.f32 %0, %1;" : "=r"(r) : "f"(f));
    return r;
}
__device__ __forceinline__ void mma_tf32(float* c, const uint32_t* a, const uint32_t* b) {
    asm volatile(
        "mma.sync.aligned.m16n8k8.row.col.f32.tf32.tf32.f32 "
        "{%0,%1,%2,%3}, {%4,%5,%6,%7}, {%8,%9}, {%0,%1,%2,%3};"
        : "+f"(c[0]), "+f"(c[1]), "+f"(c[2]), "+f"(c[3])
        : "r"(a[0]), "r"(a[1]), "r"(a[2]), "r"(a[3]), "r"(b[0]), "r"(b[1]));
}

// ---------------- HMMA tf32 GEMM tile: C[128 rows, 128 cols] ----------------
// A: [N_NODES][128] row-major. Bt: [128 n][128 k] row-major (i.e. C = A @ Bt^T).
#define KC 32
#define ASTRIDE 36  // 32 + 4 pad; bank-conflict-free fragment loads

template <bool HASBIAS>
__device__ __forceinline__ void hmma_tile(
    const float* __restrict__ A, const float* __restrict__ Bt,
    const float* __restrict__ bias, float* __restrict__ C, int ldc, int ccol0)
{
    __shared__ uint32_t As[128 * ASTRIDE];
    __shared__ uint32_t Bs[128 * ASTRIDE];
    const int tid = threadIdx.x, lane = tid & 31, w = tid >> 5;
    const int wm = w & 3, wn = w >> 2;
    const int gid = lane >> 2, tg = lane & 3;
    const int row0 = blockIdx.x * 128;

    float c[2][8][4];
#pragma unroll
    for (int i = 0; i < 2; i++)
#pragma unroll
        for (int j = 0; j < 8; j++)
#pragma unroll
            for (int q = 0; q < 4; q++) c[i][j][q] = 0.f;

#pragma unroll
    for (int kp = 0; kp < 4; kp++) {
        if (kp) __syncthreads();
        // stage A and B K-chunk (tf32-rounded)
#pragma unroll
        for (int q = tid; q < 1024; q += 256) {
            int r = q >> 3, k4 = (q & 7) << 2;
            int gr = row0 + r;
            if (gr >= N_NODES) gr = N_NODES - 1;
            float4 va = *(const float4*)(A + (size_t)gr * HIDDEN + kp * KC + k4);
            uint4 ua = make_uint4(f2tf32(va.x), f2tf32(va.y), f2tf32(va.z), f2tf32(va.w));
            *(uint4*)(As + r * ASTRIDE + k4) = ua;
            float4 vb = *(const float4*)(Bt + (size_t)r * HIDDEN + kp * KC + k4);
            uint4 ub = make_uint4(f2tf32(vb.x), f2tf32(vb.y), f2tf32(vb.z), f2tf32(vb.w));
            *(uint4*)(Bs + r * ASTRIDE + k4) = ub;
        }
        __syncthreads();
#pragma unroll
        for (int ks = 0; ks < 4; ks++) {
            int k0 = ks * 8;
            uint32_t af[2][4];
#pragma unroll
            for (int mt = 0; mt < 2; mt++) {
                int rb = wm * 32 + mt * 16;
                af[mt][0] = As[(rb + gid) * ASTRIDE + k0 + tg];
                af[mt][1] = As[(rb + gid + 8) * ASTRIDE + k0 + tg];
                af[mt][2] = As[(rb + gid) * ASTRIDE + k0 + tg + 4];
                af[mt][3] = As[(rb + gid + 8) * ASTRIDE + k0 + tg + 4];
            }
            uint32_t bf[8][2];
#pragma unroll
            for (int nt = 0; nt < 8; nt++) {
                int nb = wn * 64 + nt * 8 + gid;
                bf[nt][0] = Bs[nb * ASTRIDE + k0 + tg];
                bf[nt][1] = Bs[nb * ASTRIDE + k0 + tg + 4];
            }
#pragma unroll
            for (int mt = 0; mt < 2; mt++)
#pragma unroll
                for (int nt = 0; nt < 8; nt++) mma_tf32(c[mt][nt], af[mt], bf[nt]);
        }
    }

    // epilogue
#pragma unroll
    for (int mt = 0; mt < 2; mt++) {
        int r1 = row0 + wm * 32 + mt * 16 + gid;
        int r2 = r1 + 8;
#pragma unroll
        for (int nt = 0; nt < 8; nt++) {
            int coli = wn * 64 + nt * 8 + tg * 2;  // in-tile column
            float b0 = 0.f, b1 = 0.f;
            if (HASBIAS) { b0 = bias[coli]; b1 = bias[coli + 1]; }
            if (r1 < N_NODES) {
                float2 v = make_float2(c[mt][nt][0] + b0, c[mt][nt][1] + b1);
                *(float2*)(C + (size_t)r1 * ldc + ccol0 + coli) = v;
            }
            if (r2 < N_NODES) {
                float2 v = make_float2(c[mt][nt][2] + b0, c[mt][nt][3] + b1);
                *(float2*)(C + (size_t)r2 * ldc + ccol0 + coli) = v;
            }
        }
    }
}

__global__ void __launch_bounds__(256, 2) k_mma_msg() {
    hmma_tile<false>(d_h, d_Wt, nullptr, d_m, HIDDEN, 0);
}

__global__ void __launch_bounds__(256, 2) k_mma_gru(
    const float* __restrict__ wih, const float* __restrict__ whh,
    const float* __restrict__ bih, const float* __restrict__ bhh)
{
    int p = blockIdx.y;  // 0..5
    const float* A = (p < 3) ? d_agg : d_h;
    const float* B = ((p < 3) ? wih : whh) + (size_t)(p % 3) * 128 * 128;
    const float* bias = ((p < 3) ? bih : bhh) + (p % 3) * 128;
    hmma_tile<true>(A, B, bias, d_G, 6 * HIDDEN, p * 128);
}

__global__ void __launch_bounds__(256, 2) k_mma_fc1(
    const float* __restrict__ w, const float* __restrict__ b) {
    hmma_tile<true>(d_h, w, b, d_m, HIDDEN, 0);
}

// one-off 128x128 weight transpose: d_Wt[n][k] = W[k][n]
__global__ void k_transpose(const float* __restrict__ W) {
    __shared__ float t[32][33];
    int bx = blockIdx.x & 3, by = blockIdx.x >> 2;  // 16 blocks of 32x32
    int x = threadIdx.x & 31, y = threadIdx.x >> 5;  // 256 thr: 32x8
#pragma unroll
    for (int i = 0; i < 32; i += 8)
        t[y + i][x] = W[(size_t)(by * 32 + y + i) * 128 + bx * 32 + x];
    __syncthreads();
#pragma unroll
    for (int i = 0; i < 32; i += 8)
        d_Wt[(size_t)(bx * 32 + y + i) * 128 + by * 32 + x] = t[x][y + i];
}

// ---------------- setup kernels ----------------
__global__ void k_init() {
    int i = blockIdx.x * blockDim.x + threadIdx.x;
    if (i < N_NODES) d_deg[i] = 0;
    if (i < NUM_GRAPHS * HIDDEN) d_pool[i] = 0.f;
    if (i < NUM_GRAPHS) d_cnt[i] = 0;
    if (i < HIDDEN) { d_sum[i] = 0.f; d_sumsq[i] = 0.f; }
}

__global__ void k_copy_x(const float* __restrict__ x) {
    int i = blockIdx.x * blockDim.x + threadIdx.x;
    ((float4*)d_h)[i] = ((const float4*)x)[i];
}

__global__ void k_edges(const int* __restrict__ e) {
    int i = blockIdx.x * blockDim.x + threadIdx.x;
    int s = e[i];
    int d = e[N_EDGES + i];
    d_src[i] = s;
    d_dst[i] = d;
    atomicAdd(&d_deg[d], 1);
}

__global__ void k_batch_hist(const int* __restrict__ batch) {
    int i = blockIdx.x * blockDim.x + threadIdx.x;
    if (i < N_NODES) atomicAdd(&d_cnt[batch[i]], 1);
}

__global__ void k_scan() {
    __shared__ int s[1024];
    __shared__ int carry;
    int t = threadIdx.x;
    if (t == 0) carry = 0;
    __syncthreads();
    for (int base = 0; base < N_NODES; base += 1024) {
        int idx = base + t;
        int v = (idx < N_NODES) ? d_deg[idx] : 0;
        s[t] = v;
        __syncthreads();
        for (int off = 1; off < 1024; off <<= 1) {
            int tmp = (t >= off) ? s[t - off] : 0;
            __syncthreads();
            s[t] += tmp;
            __syncthreads();
        }
        if (idx < N_NODES) {
            int ex = carry + s[t] - v;
            d_rowptr[idx] = ex;
            d_cursor[idx] = ex;
        }
        __syncthreads();
        if (t == 0) carry += s[1023];
        __syncthreads();
    }
    if (t == 0) d_rowptr[N_NODES] = carry;
}

__global__ void k_csr_fill() {
    int i = blockIdx.x * blockDim.x + threadIdx.x;
    int pos = atomicAdd(&d_cursor[d_dst[i]], 1);
    d_colidx[pos] = d_src[i];
}

// ---------------- CSR aggregate: one warp per destination node ----------------
__global__ void k_aggregate() {
    int warp = (blockIdx.x * blockDim.x + threadIdx.x) >> 5;
    int lane = threadIdx.x & 31;
    if (warp >= N_NODES) return;
    int beg = d_rowptr[warp], end = d_rowptr[warp + 1];
    float4 acc = make_float4(0.f, 0.f, 0.f, 0.f);
    for (int e = beg; e < end; e++) {
        int src = d_colidx[e];
        float4 v = *(const float4*)(d_m + (size_t)src * HIDDEN + lane * 4);
        acc.x += v.x; acc.y += v.y; acc.z += v.z; acc.w += v.w;
    }
    *(float4*)(d_agg + (size_t)warp * HIDDEN + lane * 4) = acc;
}

// ---------------- GRU elementwise update ----------------
__global__ void k_gru_update() {
    int t = blockIdx.x * blockDim.x + threadIdx.x;
    int n = t >> 5, c4 = (t & 31) << 2;
    const float* g = d_G + (size_t)n * (6 * HIDDEN) + c4;
    float4 ir = *(const float4*)(g + 0 * HIDDEN);
    float4 iz = *(const float4*)(g + 1 * HIDDEN);
    float4 in_ = *(const float4*)(g + 2 * HIDDEN);
    float4 hr = *(const float4*)(g + 3 * HIDDEN);
    float4 hz = *(const float4*)(g + 4 * HIDDEN);
    float4 hn = *(const float4*)(g + 5 * HIDDEN);
    float* hp = d_h + (size_t)n * HIDDEN + c4;
    float4 h = *(float4*)hp;
    float4 o;
    {
        float r = sigm_f(ir.x + hr.x), z = sigm_f(iz.x + hz.x);
        float nn = tanh_f(in_.x + r * hn.x);
        o.x = (1.f - z) * nn + z * h.x;
    }
    {
        float r = sigm_f(ir.y + hr.y), z = sigm_f(iz.y + hz.y);
        float nn = tanh_f(in_.y + r * hn.y);
        o.y = (1.f - z) * nn + z * h.y;
    }
    {
        float r = sigm_f(ir.z + hr.z), z = sigm_f(iz.z + hz.z);
        float nn = tanh_f(in_.z + r * hn.z);
        o.z = (1.f - z) * nn + z * h.z;
    }
    {
        float r = sigm_f(ir.w + hr.w), z = sigm_f(iz.w + hz.w);
        float nn = tanh_f(in_.w + r * hn.w);
        o.w = (1.f - z) * nn + z * h.w;
    }
    *(float4*)hp = o;
}

// ---------------- batchnorm + relu + mean pool + classifier ----------------
__global__ void k_bn_stats() {
    int c = threadIdx.x;
    int n0 = blockIdx.x * 500;
    int n1 = n0 + 500;
    float s = 0.f, s2 = 0.f;
    for (int n = n0; n < n1; n++) {
        float v = d_m[(size_t)n * HIDDEN + c];
        s += v;
        s2 += v * v;
    }
    atomicAdd(&d_sum[c], s);
    atomicAdd(&d_sumsq[c], s2);
}

__global__ void k_bn_final() {
    int c = threadIdx.x;
    float mu = d_sum[c] / (float)N_NODES;
    float var = d_sumsq[c] / (float)N_NODES - mu * mu;
    d_mean[c] = mu;
    d_rstd[c] = rsqrtf(var + BN_EPS);
}

__global__ void k_pool(const int* __restrict__ batch,
                       const float* __restrict__ gamma,
                       const float* __restrict__ beta) {
    int c = threadIdx.x;
    int n0 = blockIdx.x * 512;
    int n1 = n0 + 512;
    if (n1 > N_NODES) n1 = N_NODES;
    if (n0 >= N_NODES) return;
    float sc = gamma[c] * d_rstd[c];
    float mu = d_mean[c];
    float be = beta[c];
    float acc = 0.f;
    int cur = batch[n0];
    for (int n = n0; n < n1; n++) {
        int bb = batch[n];
        if (bb != cur) {
            atomicAdd(&d_pool[cur * HIDDEN + c], acc);
            acc = 0.f;
            cur = bb;
        }
        float v = (d_m[(size_t)n * HIDDEN + c] - mu) * sc + be;
        acc += fmaxf(v, 0.f);
    }
    atomicAdd(&d_pool[cur * HIDDEN + c], acc);
}

__global__ void k_final(const float* __restrict__ w2, const float* __restrict__ b2,
                        float* __restrict__ out) {
    __shared__ float sf[HIDDEN];
    __shared__ float lg[NUM_CLASSES];
    int g = blockIdx.x, t = threadIdx.x;
    float cnt = fmaxf((float)d_cnt[g], 1.f);
    sf[t] = d_pool[g * HIDDEN + t] / cnt;
    __syncthreads();
    if (t < NUM_CLASSES) {
        float s = b2[t];
        for (int k = 0; k < HIDDEN; k++) s += sf[k] * w2[t * HIDDEN + k];
        lg[t] = s;
    }
    __syncthreads();
    if (t == 0) {
        float mx = -1e30f;
        for (int c = 0; c < NUM_CLASSES; c++) mx = fmaxf(mx, lg[c]);
        float se = 0.f;
        for (int c = 0; c < NUM_CLASSES; c++) se += expf(lg[c] - mx);
        float lse = mx + logf(se);
        for (int c = 0; c < NUM_CLASSES; c++) out[g * NUM_CLASSES + c] = lg[c] - lse;
    }
}

// ---------------- launch ----------------
extern "C" void kernel_launch(void* const* d_in, const int* in_sizes, int n_in,
                              void* d_out, int out_size) {
    const float* x     = (const float*)d_in[0];
    const int*   ei    = (const int*)d_in[1];
    const int*   bat   = (const int*)d_in[2];
    const float* ggnn  = (const float*)d_in[3];
    const float* wih   = (const float*)d_in[4];
    const float* whh   = (const float*)d_in[5];
    const float* bih   = (const float*)d_in[6];
    const float* bhh   = (const float*)d_in[7];
    const float* fc1w  = (const float*)d_in[8];
    const float* fc1b  = (const float*)d_in[9];
    const float* gamma = (const float*)d_in[10];
    const float* beta  = (const float*)d_in[11];
    const float* fc2w  = (const float*)d_in[12];
    const float* fc2b  = (const float*)d_in[13];
    float* out = (float*)d_out;

    k_init<<<(N_NODES + 255) / 256, 256>>>();
    k_copy_x<<<(N_NODES * HIDDEN / 4) / 256, 256>>>(x);
    k_edges<<<N_EDGES / 256, 256>>>(ei);
    k_batch_hist<<<(N_NODES + 255) / 256, 256>>>(bat);
    k_scan<<<1, 1024>>>();
    k_csr_fill<<<N_EDGES / 256, 256>>>();

    const int gb = (N_NODES + 127) / 128;  // 782
    for (int l = 0; l < NUM_LAYERS; l++) {
        k_transpose<<<16, 256>>>(ggnn + (size_t)l * HIDDEN * HIDDEN);
        k_mma_msg<<<gb, 256>>>();
        k_aggregate<<<(N_NODES * 32) / 256, 256>>>();
        k_mma_gru<<<dim3(gb, 6), 256>>>(wih, whh, bih, bhh);
        k_gru_update<<<(N_NODES * 32) / 256, 256>>>();
    }

    k_mma_fc1<<<gb, 256>>>(fc1w, fc1b);
    k_bn_stats<<<200, 128>>>();
    k_bn_final<<<1, 128>>>();
    k_pool<<<(N_NODES + 511) / 512, 128>>>(bat, gamma, beta);
    k_final<<<NUM_GRAPHS, 128>>>(fc2w, fc2b, out);
}

// round 5
// speedup vs baseline: 2.1101x; 1.2217x over previous
#include <cuda_runtime.h>
#include <cstdint>

#define N_NODES 100000
#define N_EDGES 1600000
#define HIDDEN 128
#define NUM_CLASSES 10
#define NUM_LAYERS 4
#define NUM_GRAPHS 200
#define BN_EPS 1e-5f

// ---------------- scratch (static device arrays: no allocations) ----------------
__device__ float d_h[(size_t)N_NODES * HIDDEN];
__device__ float d_m[(size_t)N_NODES * HIDDEN];
__device__ float d_agg[(size_t)N_NODES * HIDDEN];
__device__ float d_Wt[HIDDEN * HIDDEN];
__device__ int d_src[N_EDGES];
__device__ int d_dst[N_EDGES];
__device__ int d_deg[N_NODES];
__device__ int d_rowptr[N_NODES + 1];
__device__ int d_cursor[N_NODES];
__device__ int d_colidx[N_EDGES];
__device__ int d_blocksum[128];
__device__ int d_blockoff[128];
__device__ float d_sum[HIDDEN], d_sumsq[HIDDEN], d_mean[HIDDEN], d_rstd[HIDDEN];
__device__ float d_pool[NUM_GRAPHS * HIDDEN];
__device__ int d_cnt[NUM_GRAPHS];

// ---------------- helpers ----------------
__device__ __forceinline__ float sigm_f(float x) {
    return __fdividef(1.f, 1.f + __expf(-x));
}
__device__ __forceinline__ float tanh_f(float x) {
    return 1.f - __fdividef(2.f, __expf(2.f * x) + 1.f);
}
__device__ __forceinline__ uint32_t f2tf32(float f) {
    uint32_t r;
    asm("cvt.rna.tf32.f32 %0, %1;" : "=r"(r) : "f"(f));
    return r;
}
__device__ __forceinline__ void mma_tf32(float* c, const uint32_t* a, const uint32_t* b) {
    asm volatile(
        "mma.sync.aligned.m16n8k8.row.col.f32.tf32.tf32.f32 "
        "{%0,%1,%2,%3}, {%4,%5,%6,%7}, {%8,%9}, {%0,%1,%2,%3};"
        : "+f"(c[0]), "+f"(c[1]), "+f"(c[2]), "+f"(c[3])
        : "r"(a[0]), "r"(a[1]), "r"(a[2]), "r"(a[3]), "r"(b[0]), "r"(b[1]));
}

#define ASTRIDE 36

// ============ fused GRU layer: h = GRU([agg|h] gates), 128 rows/block, 512 thr ============
// Gate g GEMM: out[128x128] = agg@Wih_g^T + h@Whh_g^T  over concat K=256 (8 chunks of 32).
// Pass order: r (g=0) -> n (g=2, split accumulators) -> z (g=1, update h in-place).
__device__ __forceinline__ void gru_stage_chunk(
    uint32_t* As, uint32_t* Bs, int row0, int cc, int g,
    const float* __restrict__ wih, const float* __restrict__ whh)
{
    const float* Aq = (cc < 4) ? d_agg : d_h;
    const float* Bq = (cc < 4) ? wih : whh;
    const int kofs = (cc & 3) * 32;
    const int tid = threadIdx.x;
#pragma unroll
    for (int q = tid; q < 1024; q += 512) {
        int r = q >> 3, k4 = (q & 7) << 2;
        int gr = row0 + r;
        if (gr >= N_NODES) gr = N_NODES - 1;
        float4 va = *(const float4*)(Aq + (size_t)gr * HIDDEN + kofs + k4);
        *(uint4*)(As + r * ASTRIDE + k4) =
            make_uint4(f2tf32(va.x), f2tf32(va.y), f2tf32(va.z), f2tf32(va.w));
        float4 vb = *(const float4*)(Bq + (size_t)(g * 128 + r) * HIDDEN + kofs + k4);
        *(uint4*)(Bs + r * ASTRIDE + k4) =
            make_uint4(f2tf32(vb.x), f2tf32(vb.y), f2tf32(vb.z), f2tf32(vb.w));
    }
}

__device__ __forceinline__ void gru_mma_chunk(
    const uint32_t* As, const uint32_t* Bs, float (*c)[4],
    int wm, int wn, int gid, int tg)
{
#pragma unroll
    for (int ks = 0; ks < 4; ks++) {
        int k0 = ks * 8;
        uint32_t af[4];
        af[0] = As[(wm * 16 + gid) * ASTRIDE + k0 + tg];
        af[1] = As[(wm * 16 + gid + 8) * ASTRIDE + k0 + tg];
        af[2] = As[(wm * 16 + gid) * ASTRIDE + k0 + tg + 4];
        af[3] = As[(wm * 16 + gid + 8) * ASTRIDE + k0 + tg + 4];
#pragma unroll
        for (int nt = 0; nt < 8; nt++) {
            uint32_t bf[2];
            bf[0] = Bs[(wn * 64 + nt * 8 + gid) * ASTRIDE + k0 + tg];
            bf[1] = Bs[(wn * 64 + nt * 8 + gid) * ASTRIDE + k0 + tg + 4];
            mma_tf32(c[nt], af, bf);
        }
    }
}

__global__ void __launch_bounds__(512, 1) k_gru_fused(
    const float* __restrict__ wih, const float* __restrict__ whh,
    const float* __restrict__ bih, const float* __restrict__ bhh)
{
    __shared__ uint32_t As[128 * ASTRIDE];
    __shared__ uint32_t Bs[128 * ASTRIDE];
    const int tid = threadIdx.x, lane = tid & 31, w = tid >> 5;
    const int wm = w & 7, wn = w >> 3;         // 8 m-strips x 2 n-strips
    const int gid = lane >> 2, tg = lane & 3;
    const int row0 = blockIdx.x * 128;

    float rr[8][4], nn[8][4];

    // ---- pass R (g=0) ----
    {
        float c[8][4];
#pragma unroll
        for (int j = 0; j < 8; j++)
#pragma unroll
            for (int q = 0; q < 4; q++) c[j][q] = 0.f;
#pragma unroll
        for (int cc = 0; cc < 8; cc++) {
            __syncthreads();
            gru_stage_chunk(As, Bs, row0, cc, 0, wih, whh);
            __syncthreads();
            gru_mma_chunk(As, Bs, c, wm, wn, gid, tg);
        }
#pragma unroll
        for (int nt = 0; nt < 8; nt++) {
            int coli = wn * 64 + nt * 8 + tg * 2;
            float b0 = bih[coli] + bhh[coli];
            float b1 = bih[coli + 1] + bhh[coli + 1];
            rr[nt][0] = sigm_f(c[nt][0] + b0);
            rr[nt][1] = sigm_f(c[nt][1] + b1);
            rr[nt][2] = sigm_f(c[nt][2] + b0);
            rr[nt][3] = sigm_f(c[nt][3] + b1);
        }
    }

    // ---- pass N (g=2): separate i_n / h_n accumulators ----
    {
        float ci[8][4], ch[8][4];
#pragma unroll
        for (int j = 0; j < 8; j++)
#pragma unroll
            for (int q = 0; q < 4; q++) { ci[j][q] = 0.f; ch[j][q] = 0.f; }
#pragma unroll
        for (int cc = 0; cc < 8; cc++) {
            __syncthreads();
            gru_stage_chunk(As, Bs, row0, cc, 2, wih, whh);
            __syncthreads();
            gru_mma_chunk(As, Bs, (cc < 4) ? ci : ch, wm, wn, gid, tg);
        }
#pragma unroll
        for (int nt = 0; nt < 8; nt++) {
            int coli = wn * 64 + nt * 8 + tg * 2;
            float bi0 = bih[256 + coli], bi1 = bih[256 + coli + 1];
            float bh0 = bhh[256 + coli], bh1 = bhh[256 + coli + 1];
            nn[nt][0] = tanh_f(ci[nt][0] + bi0 + rr[nt][0] * (ch[nt][0] + bh0));
            nn[nt][1] = tanh_f(ci[nt][1] + bi1 + rr[nt][1] * (ch[nt][1] + bh1));
            nn[nt][2] = tanh_f(ci[nt][2] + bi0 + rr[nt][2] * (ch[nt][2] + bh0));
            nn[nt][3] = tanh_f(ci[nt][3] + bi1 + rr[nt][3] * (ch[nt][3] + bh1));
        }
    }

    // ---- pass Z (g=1) + in-place h update ----
    {
        float c[8][4];
#pragma unroll
        for (int j = 0; j < 8; j++)
#pragma unroll
            for (int q = 0; q < 4; q++) c[j][q] = 0.f;
#pragma unroll
        for (int cc = 0; cc < 8; cc++) {
            __syncthreads();
            gru_stage_chunk(As, Bs, row0, cc, 1, wih, whh);
            __syncthreads();
            gru_mma_chunk(As, Bs, c, wm, wn, gid, tg);
        }
        int r1 = row0 + wm * 16 + gid;
        int r2 = r1 + 8;
#pragma unroll
        for (int nt = 0; nt < 8; nt++) {
            int coli = wn * 64 + nt * 8 + tg * 2;
            float b0 = bih[128 + coli] + bhh[128 + coli];
            float b1 = bih[128 + coli + 1] + bhh[128 + coli + 1];
            if (r1 < N_NODES) {
                float* hp = d_h + (size_t)r1 * HIDDEN + coli;
                float2 h = *(float2*)hp;
                float z0 = sigm_f(c[nt][0] + b0), z1 = sigm_f(c[nt][1] + b1);
                float2 o;
                o.x = (1.f - z0) * nn[nt][0] + z0 * h.x;
                o.y = (1.f - z1) * nn[nt][1] + z1 * h.y;
                *(float2*)hp = o;
            }
            if (r2 < N_NODES) {
                float* hp = d_h + (size_t)r2 * HIDDEN + coli;
                float2 h = *(float2*)hp;
                float z0 = sigm_f(c[nt][2] + b0), z1 = sigm_f(c[nt][3] + b1);
                float2 o;
                o.x = (1.f - z0) * nn[nt][2] + z0 * h.x;
                o.y = (1.f - z1) * nn[nt][3] + z1 * h.y;
                *(float2*)hp = o;
            }
        }
    }
}

// ---------------- HMMA tf32 GEMM tile (msg / fc1), 256 thr, occ 2 ----------------
template <bool HASBIAS>
__device__ __forceinline__ void hmma_tile(
    const float* __restrict__ A, const float* __restrict__ Bt,
    const float* __restrict__ bias, float* __restrict__ C, int ldc, int ccol0)
{
    __shared__ uint32_t As[128 * ASTRIDE];
    __shared__ uint32_t Bs[128 * ASTRIDE];
    const int tid = threadIdx.x, lane = tid & 31, w = tid >> 5;
    const int wm = w & 3, wn = w >> 2;
    const int gid = lane >> 2, tg = lane & 3;
    const int row0 = blockIdx.x * 128;

    float c[2][8][4];
#pragma unroll
    for (int i = 0; i < 2; i++)
#pragma unroll
        for (int j = 0; j < 8; j++)
#pragma unroll
            for (int q = 0; q < 4; q++) c[i][j][q] = 0.f;

#pragma unroll
    for (int kp = 0; kp < 4; kp++) {
        if (kp) __syncthreads();
#pragma unroll
        for (int q = tid; q < 1024; q += 256) {
            int r = q >> 3, k4 = (q & 7) << 2;
            int gr = row0 + r;
            if (gr >= N_NODES) gr = N_NODES - 1;
            float4 va = *(const float4*)(A + (size_t)gr * HIDDEN + kp * 32 + k4);
            *(uint4*)(As + r * ASTRIDE + k4) =
                make_uint4(f2tf32(va.x), f2tf32(va.y), f2tf32(va.z), f2tf32(va.w));
            float4 vb = *(const float4*)(Bt + (size_t)r * HIDDEN + kp * 32 + k4);
            *(uint4*)(Bs + r * ASTRIDE + k4) =
                make_uint4(f2tf32(vb.x), f2tf32(vb.y), f2tf32(vb.z), f2tf32(vb.w));
        }
        __syncthreads();
#pragma unroll
        for (int ks = 0; ks < 4; ks++) {
            int k0 = ks * 8;
            uint32_t af[2][4];
#pragma unroll
            for (int mt = 0; mt < 2; mt++) {
                int rb = wm * 32 + mt * 16;
                af[mt][0] = As[(rb + gid) * ASTRIDE + k0 + tg];
                af[mt][1] = As[(rb + gid + 8) * ASTRIDE + k0 + tg];
                af[mt][2] = As[(rb + gid) * ASTRIDE + k0 + tg + 4];
                af[mt][3] = As[(rb + gid + 8) * ASTRIDE + k0 + tg + 4];
            }
#pragma unroll
            for (int nt = 0; nt < 8; nt++) {
                uint32_t bf[2];
                int nb = wn * 64 + nt * 8 + gid;
                bf[0] = Bs[nb * ASTRIDE + k0 + tg];
                bf[1] = Bs[nb * ASTRIDE + k0 + tg + 4];
#pragma unroll
                for (int mt = 0; mt < 2; mt++) mma_tf32(c[mt][nt], af[mt], bf);
            }
        }
    }

#pragma unroll
    for (int mt = 0; mt < 2; mt++) {
        int r1 = row0 + wm * 32 + mt * 16 + gid;
        int r2 = r1 + 8;
#pragma unroll
        for (int nt = 0; nt < 8; nt++) {
            int coli = wn * 64 + nt * 8 + tg * 2;
            float b0 = 0.f, b1 = 0.f;
            if (HASBIAS) { b0 = bias[coli]; b1 = bias[coli + 1]; }
            if (r1 < N_NODES) {
                float2 v = make_float2(c[mt][nt][0] + b0, c[mt][nt][1] + b1);
                *(float2*)(C + (size_t)r1 * ldc + ccol0 + coli) = v;
            }
            if (r2 < N_NODES) {
                float2 v = make_float2(c[mt][nt][2] + b0, c[mt][nt][3] + b1);
                *(float2*)(C + (size_t)r2 * ldc + ccol0 + coli) = v;
            }
        }
    }
}

__global__ void __launch_bounds__(256, 2) k_mma_msg() {
    hmma_tile<false>(d_h, d_Wt, nullptr, d_m, HIDDEN, 0);
}

__global__ void __launch_bounds__(256, 2) k_mma_fc1(
    const float* __restrict__ w, const float* __restrict__ b) {
    hmma_tile<true>(d_h, w, b, d_m, HIDDEN, 0);
}

// one-off 128x128 weight transpose: d_Wt[n][k] = W[k][n]
__global__ void k_transpose(const float* __restrict__ W) {
    __shared__ float t[32][33];
    int bx = blockIdx.x & 3, by = blockIdx.x >> 2;
    int x = threadIdx.x & 31, y = threadIdx.x >> 5;
#pragma unroll
    for (int i = 0; i < 32; i += 8)
        t[y + i][x] = W[(size_t)(by * 32 + y + i) * 128 + bx * 32 + x];
    __syncthreads();
#pragma unroll
    for (int i = 0; i < 32; i += 8)
        d_Wt[(size_t)(bx * 32 + y + i) * 128 + by * 32 + x] = t[x][y + i];
}

// ---------------- setup kernels ----------------
__global__ void k_init() {
    int i = blockIdx.x * blockDim.x + threadIdx.x;
    if (i < N_NODES) d_deg[i] = 0;
    if (i < NUM_GRAPHS * HIDDEN) d_pool[i] = 0.f;
    if (i < NUM_GRAPHS) d_cnt[i] = 0;
    if (i < HIDDEN) { d_sum[i] = 0.f; d_sumsq[i] = 0.f; }
}

__global__ void k_copy_x(const float* __restrict__ x) {
    int i = blockIdx.x * blockDim.x + threadIdx.x;
    ((float4*)d_h)[i] = ((const float4*)x)[i];
}

__global__ void k_edges(const int* __restrict__ e) {
    int i = blockIdx.x * blockDim.x + threadIdx.x;
    int s = e[i];
    int d = e[N_EDGES + i];
    d_src[i] = s;
    d_dst[i] = d;
    atomicAdd(&d_deg[d], 1);
}

__global__ void k_batch_hist(const int* __restrict__ batch) {
    __shared__ int hc[NUM_GRAPHS];
    for (int i = threadIdx.x; i < NUM_GRAPHS; i += blockDim.x) hc[i] = 0;
    __syncthreads();
    int idx = blockIdx.x * blockDim.x + threadIdx.x;
    if (idx < N_NODES) atomicAdd(&hc[batch[idx]], 1);
    __syncthreads();
    for (int i = threadIdx.x; i < NUM_GRAPHS; i += blockDim.x)
        if (hc[i]) atomicAdd(&d_cnt[i], hc[i]);
}

// 3-phase parallel scan of d_deg -> d_rowptr / d_cursor
__global__ void k_scan1() {  // 98 blocks x 1024
    __shared__ int sh[32];
    int lane = threadIdx.x & 31, warp = threadIdx.x >> 5;
    int idx = blockIdx.x * 1024 + threadIdx.x;
    int v = (idx < N_NODES) ? d_deg[idx] : 0;
#pragma unroll
    for (int o = 16; o; o >>= 1) v += __shfl_down_sync(0xFFFFFFFFu, v, o);
    if (lane == 0) sh[warp] = v;
    __syncthreads();
    if (warp == 0) {
        v = sh[lane];
#pragma unroll
        for (int o = 16; o; o >>= 1) v += __shfl_down_sync(0xFFFFFFFFu, v, o);
        if (lane == 0) d_blocksum[blockIdx.x] = v;
    }
}

__global__ void k_scan2() {  // 1 block x 128
    __shared__ int s[128];
    int t = threadIdx.x;
    int v = (t < 98) ? d_blocksum[t] : 0;
    s[t] = v;
    __syncthreads();
#pragma unroll
    for (int o = 1; o < 128; o <<= 1) {
        int tmp = (t >= o) ? s[t - o] : 0;
        __syncthreads();
        s[t] += tmp;
        __syncthreads();
    }
    if (t < 98) d_blockoff[t] = s[t] - v;
    if (t == 0) d_rowptr[N_NODES] = s[97];
}

__global__ void k_scan3() {  // 98 blocks x 1024
    __shared__ int s[1024];
    int t = threadIdx.x;
    int idx = blockIdx.x * 1024 + t;
    int v = (idx < N_NODES) ? d_deg[idx] : 0;
    s[t] = v;
    __syncthreads();
#pragma unroll
    for (int o = 1; o < 1024; o <<= 1) {
        int tmp = (t >= o) ? s[t - o] : 0;
        __syncthreads();
        s[t] += tmp;
        __syncthreads();
    }
    if (idx < N_NODES) {
        int ex = d_blockoff[blockIdx.x] + s[t] - v;
        d_rowptr[idx] = ex;
        d_cursor[idx] = ex;
    }
}

__global__ void k_csr_fill() {
    int i = blockIdx.x * blockDim.x + threadIdx.x;
    int pos = atomicAdd(&d_cursor[d_dst[i]], 1);
    d_colidx[pos] = d_src[i];
}

// ---------------- CSR aggregate: one warp per destination node ----------------
__global__ void k_aggregate() {
    int warp = (blockIdx.x * blockDim.x + threadIdx.x) >> 5;
    int lane = threadIdx.x & 31;
    if (warp >= N_NODES) return;
    int beg = d_rowptr[warp], end = d_rowptr[warp + 1];
    float4 acc = make_float4(0.f, 0.f, 0.f, 0.f);
    for (int e = beg; e < end; e++) {
        int src = d_colidx[e];
        float4 v = *(const float4*)(d_m + (size_t)src * HIDDEN + lane * 4);
        acc.x += v.x; acc.y += v.y; acc.z += v.z; acc.w += v.w;
    }
    *(float4*)(d_agg + (size_t)warp * HIDDEN + lane * 4) = acc;
}

// ---------------- batchnorm + relu + mean pool + classifier ----------------
__global__ void k_bn_stats() {
    int c = threadIdx.x;
    int n0 = blockIdx.x * 500;
    int n1 = n0 + 500;
    float s = 0.f, s2 = 0.f;
    for (int n = n0; n < n1; n++) {
        float v = d_m[(size_t)n * HIDDEN + c];
        s += v;
        s2 += v * v;
    }
    atomicAdd(&d_sum[c], s);
    atomicAdd(&d_sumsq[c], s2);
}

__global__ void k_bn_final() {
    int c = threadIdx.x;
    float mu = d_sum[c] / (float)N_NODES;
    float var = d_sumsq[c] / (float)N_NODES - mu * mu;
    d_mean[c] = mu;
    d_rstd[c] = rsqrtf(var + BN_EPS);
}

__global__ void k_pool(const int* __restrict__ batch,
                       const float* __restrict__ gamma,
                       const float* __restrict__ beta) {
    int c = threadIdx.x;
    int n0 = blockIdx.x * 512;
    int n1 = n0 + 512;
    if (n1 > N_NODES) n1 = N_NODES;
    if (n0 >= N_NODES) return;
    float sc = gamma[c] * d_rstd[c];
    float mu = d_mean[c];
    float be = beta[c];
    float acc = 0.f;
    int cur = batch[n0];
    for (int n = n0; n < n1; n++) {
        int bb = batch[n];
        if (bb != cur) {
            atomicAdd(&d_pool[cur * HIDDEN + c], acc);
            acc = 0.f;
            cur = bb;
        }
        float v = (d_m[(size_t)n * HIDDEN + c] - mu) * sc + be;
        acc += fmaxf(v, 0.f);
    }
    atomicAdd(&d_pool[cur * HIDDEN + c], acc);
}

__global__ void k_final(const float* __restrict__ w2, const float* __restrict__ b2,
                        float* __restrict__ out) {
    __shared__ float sf[HIDDEN];
    __shared__ float lg[NUM_CLASSES];
    int g = blockIdx.x, t = threadIdx.x;
    float cnt = fmaxf((float)d_cnt[g], 1.f);
    sf[t] = d_pool[g * HIDDEN + t] / cnt;
    __syncthreads();
    if (t < NUM_CLASSES) {
        float s = b2[t];
        for (int k = 0; k < HIDDEN; k++) s += sf[k] * w2[t * HIDDEN + k];
        lg[t] = s;
    }
    __syncthreads();
    if (t == 0) {
        float mx = -1e30f;
        for (int c = 0; c < NUM_CLASSES; c++) mx = fmaxf(mx, lg[c]);
        float se = 0.f;
        for (int c = 0; c < NUM_CLASSES; c++) se += expf(lg[c] - mx);
        float lse = mx + logf(se);
        for (int c = 0; c < NUM_CLASSES; c++) out[g * NUM_CLASSES + c] = lg[c] - lse;
    }
}

// ---------------- launch ----------------
extern "C" void kernel_launch(void* const* d_in, const int* in_sizes, int n_in,
                              void* d_out, int out_size) {
    const float* x     = (const float*)d_in[0];
    const int*   ei    = (const int*)d_in[1];
    const int*   bat   = (const int*)d_in[2];
    const float* ggnn  = (const float*)d_in[3];
    const float* wih   = (const float*)d_in[4];
    const float* whh   = (const float*)d_in[5];
    const float* bih   = (const float*)d_in[6];
    const float* bhh   = (const float*)d_in[7];
    const float* fc1w  = (const float*)d_in[8];
    const float* fc1b  = (const float*)d_in[9];
    const float* gamma = (const float*)d_in[10];
    const float* beta  = (const float*)d_in[11];
    const float* fc2w  = (const float*)d_in[12];
    const float* fc2b  = (const float*)d_in[13];
    float* out = (float*)d_out;

    k_init<<<(N_NODES + 255) / 256, 256>>>();
    k_copy_x<<<(N_NODES * HIDDEN / 4) / 256, 256>>>(x);
    k_edges<<<N_EDGES / 256, 256>>>(ei);
    k_batch_hist<<<98, 1024>>>(bat);
    k_scan1<<<98, 1024>>>();
    k_scan2<<<1, 128>>>();
    k_scan3<<<98, 1024>>>();
    k_csr_fill<<<N_EDGES / 256, 256>>>();

    const int gb = (N_NODES + 127) / 128;  // 782
    for (int l = 0; l < NUM_LAYERS; l++) {
        k_transpose<<<16, 256>>>(ggnn + (size_t)l * HIDDEN * HIDDEN);
        k_mma_msg<<<gb, 256>>>();
        k_aggregate<<<(N_NODES * 32) / 256, 256>>>();
        k_gru_fused<<<gb, 512>>>(wih, whh, bih, bhh);
    }

    k_mma_fc1<<<gb, 256>>>(fc1w, fc1b);
    k_bn_stats<<<200, 128>>>();
    k_bn_final<<<1, 128>>>();
    k_pool<<<(N_NODES + 511) / 512, 128>>>(bat, gamma, beta);
    k_final<<<NUM_GRAPHS, 128>>>(fc2w, fc2b, out);
}

// round 6
// speedup vs baseline: 2.3677x; 1.1221x over previous
#include <cuda_runtime.h>
#include <cstdint>

#define N_NODES 100000
#define N_EDGES 1600000
#define HIDDEN 128
#define NUM_CLASSES 10
#define NUM_LAYERS 4
#define NUM_GRAPHS 200
#define BN_EPS 1e-5f

// ---------------- scratch (static device arrays: no allocations) ----------------
__device__ float d_h[(size_t)N_NODES * HIDDEN];
__device__ float d_m[(size_t)N_NODES * HIDDEN];
__device__ float d_agg[(size_t)N_NODES * HIDDEN];
__device__ float d_Wt[NUM_LAYERS * HIDDEN * HIDDEN];
__device__ int d_src[N_EDGES];
__device__ int d_dst[N_EDGES];
__device__ int d_deg[N_NODES];
__device__ int d_rowptr[N_NODES + 1];
__device__ int d_cursor[N_NODES];
__device__ int d_colidx[N_EDGES];
__device__ int d_blocksum[128];
__device__ int d_blockoff[128];
__device__ float d_sum[HIDDEN], d_sumsq[HIDDEN], d_mean[HIDDEN], d_rstd[HIDDEN];
__device__ float d_pool[NUM_GRAPHS * HIDDEN];
__device__ int d_cnt[NUM_GRAPHS];

// ---------------- helpers ----------------
__device__ __forceinline__ float sigm_f(float x) {
    return __fdividef(1.f, 1.f + __expf(-x));
}
__device__ __forceinline__ float tanh_f(float x) {
    return 1.f - __fdividef(2.f, __expf(2.f * x) + 1.f);
}
__device__ __forceinline__ uint32_t f2tf32(float f) {
    uint32_t r;
    asm("cvt.rna.tf32.f32 %0, %1;" : "=r"(r) : "f"(f));
    return r;
}
__device__ __forceinline__ void mma_tf32(float* c, const uint32_t* a, const uint32_t* b) {
    asm volatile(
        "mma.sync.aligned.m16n8k8.row.col.f32.tf32.tf32.f32 "
        "{%0,%1,%2,%3}, {%4,%5,%6,%7}, {%8,%9}, {%0,%1,%2,%3};"
        : "+f"(c[0]), "+f"(c[1]), "+f"(c[2]), "+f"(c[3])
        : "r"(a[0]), "r"(a[1]), "r"(a[2]), "r"(a[3]), "r"(b[0]), "r"(b[1]));
}

#define ASTRIDE 36
#define ASTR_BIG 260   // [128][260] tf32 concat [agg|h]; 260%32=4 -> conflict-free frags
#define GSTR 130

// dynamic smem layout (words): AS [128*260] | BS [128*36] | GS float[128*130]
#define SM_AS_W 0
#define SM_BS_W (128 * ASTR_BIG)
#define SM_GS_W (128 * ASTR_BIG + 128 * ASTRIDE)
#define GRU_SMEM_BYTES ((128 * ASTR_BIG + 128 * ASTRIDE + 128 * GSTR) * 4)

// ============ fused GRU layer, A-resident: 128 rows/block, 512 thr ============
__global__ void __launch_bounds__(512, 1) k_gru_fused(
    const float* __restrict__ wih, const float* __restrict__ whh,
    const float* __restrict__ bih, const float* __restrict__ bhh)
{
    extern __shared__ uint32_t dsm[];
    uint32_t* AS = dsm + SM_AS_W;
    uint32_t* BS = dsm + SM_BS_W;
    float* GS = (float*)(dsm + SM_GS_W);

    const int tid = threadIdx.x, lane = tid & 31, w = tid >> 5;
    const int wm = w & 7, wn = w >> 3;  // 8 m-strips x 2 n-strips
    const int gid = lane >> 2, tg = lane & 3;
    const int row0 = blockIdx.x * 128;

    // ---- load [agg|h] tile once (tf32) ----
#pragma unroll
    for (int q = tid; q < 128 * 64; q += 512) {
        int r = q >> 6, c4 = (q & 63) << 2;  // c4: 0..252
        int gr = row0 + r;
        if (gr >= N_NODES) gr = N_NODES - 1;
        const float* sp = (c4 < 128) ? (d_agg + (size_t)gr * HIDDEN + c4)
                                     : (d_h + (size_t)gr * HIDDEN + (c4 - 128));
        float4 v = *(const float4*)sp;
        *(uint4*)(AS + r * ASTR_BIG + c4) =
            make_uint4(f2tf32(v.x), f2tf32(v.y), f2tf32(v.z), f2tf32(v.w));
    }
    __syncthreads();

    const int lr1 = wm * 16 + gid;   // local rows this thread owns
    const int lr2 = lr1 + 8;

    // ================= three gate passes: R(g=0) -> N(g=2) -> Z(g=1) =================
#pragma unroll
    for (int pass = 0; pass < 3; pass++) {
        const int g = (pass == 0) ? 0 : (pass == 1) ? 2 : 1;
        float ci[8][4], ch[8][4];  // pass N uses both; R/Z use ci only
#pragma unroll
        for (int j = 0; j < 8; j++)
#pragma unroll
            for (int q = 0; q < 4; q++) { ci[j][q] = 0.f; ch[j][q] = 0.f; }

#pragma unroll
        for (int cc = 0; cc < 8; cc++) {
            // stage weight chunk: rows g*128.., k-chunk (cc&3)*32, from wih (cc<4) / whh
            {
                const float* Bq = (cc < 4) ? wih : whh;
#pragma unroll
                for (int q = tid; q < 1024; q += 512) {
                    int r = q >> 3, k4 = (q & 7) << 2;
                    float4 vb = *(const float4*)(Bq + (size_t)(g * 128 + r) * HIDDEN +
                                                 (cc & 3) * 32 + k4);
                    *(uint4*)(BS + r * ASTRIDE + k4) =
                        make_uint4(f2tf32(vb.x), f2tf32(vb.y), f2tf32(vb.z), f2tf32(vb.w));
                }
            }
            __syncthreads();
            float(*acc)[4] = (pass == 1 && cc >= 4) ? ch : ci;
            const int abase = cc * 32;
#pragma unroll
            for (int ks = 0; ks < 4; ks++) {
                int k0 = ks * 8;
                uint32_t af[4];
                af[0] = AS[lr1 * ASTR_BIG + abase + k0 + tg];
                af[1] = AS[lr2 * ASTR_BIG + abase + k0 + tg];
                af[2] = AS[lr1 * ASTR_BIG + abase + k0 + tg + 4];
                af[3] = AS[lr2 * ASTR_BIG + abase + k0 + tg + 4];
#pragma unroll
                for (int nt = 0; nt < 8; nt++) {
                    uint32_t bf[2];
                    bf[0] = BS[(wn * 64 + nt * 8 + gid) * ASTRIDE + k0 + tg];
                    bf[1] = BS[(wn * 64 + nt * 8 + gid) * ASTRIDE + k0 + tg + 4];
                    mma_tf32(acc[nt], af, bf);
                }
            }
            __syncthreads();
        }

        // ---- pass epilogues ----
        if (pass == 0) {  // R: store sigmoid(gi_r+gh_r+biases) to GS
#pragma unroll
            for (int nt = 0; nt < 8; nt++) {
                int coli = wn * 64 + nt * 8 + tg * 2;
                float b0 = bih[coli] + bhh[coli];
                float b1 = bih[coli + 1] + bhh[coli + 1];
                GS[lr1 * GSTR + coli] = sigm_f(ci[nt][0] + b0);
                GS[lr1 * GSTR + coli + 1] = sigm_f(ci[nt][1] + b1);
                GS[lr2 * GSTR + coli] = sigm_f(ci[nt][2] + b0);
                GS[lr2 * GSTR + coli + 1] = sigm_f(ci[nt][3] + b1);
            }
        } else if (pass == 1) {  // N: nn = tanh(i_n + r*(h_n)); overwrite GS slots
#pragma unroll
            for (int nt = 0; nt < 8; nt++) {
                int coli = wn * 64 + nt * 8 + tg * 2;
                float bi0 = bih[256 + coli], bi1 = bih[256 + coli + 1];
                float bh0 = bhh[256 + coli], bh1 = bhh[256 + coli + 1];
                float r00 = GS[lr1 * GSTR + coli], r01 = GS[lr1 * GSTR + coli + 1];
                float r10 = GS[lr2 * GSTR + coli], r11 = GS[lr2 * GSTR + coli + 1];
                GS[lr1 * GSTR + coli] = tanh_f(ci[nt][0] + bi0 + r00 * (ch[nt][0] + bh0));
                GS[lr1 * GSTR + coli + 1] = tanh_f(ci[nt][1] + bi1 + r01 * (ch[nt][1] + bh1));
                GS[lr2 * GSTR + coli] = tanh_f(ci[nt][2] + bi0 + r10 * (ch[nt][2] + bh0));
                GS[lr2 * GSTR + coli + 1] = tanh_f(ci[nt][3] + bi1 + r11 * (ch[nt][3] + bh1));
            }
        } else {  // Z: h = (1-z)*n + z*h  (exact h from global)
            int gr1 = row0 + lr1, gr2 = row0 + lr2;
#pragma unroll
            for (int nt = 0; nt < 8; nt++) {
                int coli = wn * 64 + nt * 8 + tg * 2;
                float b0 = bih[128 + coli] + bhh[128 + coli];
                float b1 = bih[128 + coli + 1] + bhh[128 + coli + 1];
                if (gr1 < N_NODES) {
                    float* hp = d_h + (size_t)gr1 * HIDDEN + coli;
                    float2 h = *(float2*)hp;
                    float z0 = sigm_f(ci[nt][0] + b0), z1 = sigm_f(ci[nt][1] + b1);
                    float2 o;
                    o.x = (1.f - z0) * GS[lr1 * GSTR + coli] + z0 * h.x;
                    o.y = (1.f - z1) * GS[lr1 * GSTR + coli + 1] + z1 * h.y;
                    *(float2*)hp = o;
                }
                if (gr2 < N_NODES) {
                    float* hp = d_h + (size_t)gr2 * HIDDEN + coli;
                    float2 h = *(float2*)hp;
                    float z0 = sigm_f(ci[nt][2] + b0), z1 = sigm_f(ci[nt][3] + b1);
                    float2 o;
                    o.x = (1.f - z0) * GS[lr2 * GSTR + coli] + z0 * h.x;
                    o.y = (1.f - z1) * GS[lr2 * GSTR + coli + 1] + z1 * h.y;
                    *(float2*)hp = o;
                }
            }
        }
    }
}

// ---------------- HMMA tf32 GEMM tile (msg / fc1), 256 thr, occ 2 ----------------
template <bool HASBIAS>
__device__ __forceinline__ void hmma_tile(
    const float* __restrict__ A, const float* __restrict__ Bt,
    const float* __restrict__ bias, float* __restrict__ C, int ldc, int ccol0)
{
    __shared__ uint32_t As[128 * ASTRIDE];
    __shared__ uint32_t Bs[128 * ASTRIDE];
    const int tid = threadIdx.x, lane = tid & 31, w = tid >> 5;
    const int wm = w & 3, wn = w >> 2;
    const int gid = lane >> 2, tg = lane & 3;
    const int row0 = blockIdx.x * 128;

    float c[2][8][4];
#pragma unroll
    for (int i = 0; i < 2; i++)
#pragma unroll
        for (int j = 0; j < 8; j++)
#pragma unroll
            for (int q = 0; q < 4; q++) c[i][j][q] = 0.f;

#pragma unroll
    for (int kp = 0; kp < 4; kp++) {
        if (kp) __syncthreads();
#pragma unroll
        for (int q = tid; q < 1024; q += 256) {
            int r = q >> 3, k4 = (q & 7) << 2;
            int gr = row0 + r;
            if (gr >= N_NODES) gr = N_NODES - 1;
            float4 va = *(const float4*)(A + (size_t)gr * HIDDEN + kp * 32 + k4);
            *(uint4*)(As + r * ASTRIDE + k4) =
                make_uint4(f2tf32(va.x), f2tf32(va.y), f2tf32(va.z), f2tf32(va.w));
            float4 vb = *(const float4*)(Bt + (size_t)r * HIDDEN + kp * 32 + k4);
            *(uint4*)(Bs + r * ASTRIDE + k4) =
                make_uint4(f2tf32(vb.x), f2tf32(vb.y), f2tf32(vb.z), f2tf32(vb.w));
        }
        __syncthreads();
#pragma unroll
        for (int ks = 0; ks < 4; ks++) {
            int k0 = ks * 8;
            uint32_t af[2][4];
#pragma unroll
            for (int mt = 0; mt < 2; mt++) {
                int rb = wm * 32 + mt * 16;
                af[mt][0] = As[(rb + gid) * ASTRIDE + k0 + tg];
                af[mt][1] = As[(rb + gid + 8) * ASTRIDE + k0 + tg];
                af[mt][2] = As[(rb + gid) * ASTRIDE + k0 + tg + 4];
                af[mt][3] = As[(rb + gid + 8) * ASTRIDE + k0 + tg + 4];
            }
#pragma unroll
            for (int nt = 0; nt < 8; nt++) {
                uint32_t bf[2];
                int nb = wn * 64 + nt * 8 + gid;
                bf[0] = Bs[nb * ASTRIDE + k0 + tg];
                bf[1] = Bs[nb * ASTRIDE + k0 + tg + 4];
#pragma unroll
                for (int mt = 0; mt < 2; mt++) mma_tf32(c[mt][nt], af[mt], bf);
            }
        }
    }

#pragma unroll
    for (int mt = 0; mt < 2; mt++) {
        int r1 = row0 + wm * 32 + mt * 16 + gid;
        int r2 = r1 + 8;
#pragma unroll
        for (int nt = 0; nt < 8; nt++) {
            int coli = wn * 64 + nt * 8 + tg * 2;
            float b0 = 0.f, b1 = 0.f;
            if (HASBIAS) { b0 = bias[coli]; b1 = bias[coli + 1]; }
            if (r1 < N_NODES) {
                float2 v = make_float2(c[mt][nt][0] + b0, c[mt][nt][1] + b1);
                *(float2*)(C + (size_t)r1 * ldc + ccol0 + coli) = v;
            }
            if (r2 < N_NODES) {
                float2 v = make_float2(c[mt][nt][2] + b0, c[mt][nt][3] + b1);
                *(float2*)(C + (size_t)r2 * ldc + ccol0 + coli) = v;
            }
        }
    }
}

__global__ void __launch_bounds__(256, 2) k_mma_msg(int layer) {
    hmma_tile<false>(d_h, d_Wt + (size_t)layer * HIDDEN * HIDDEN, nullptr, d_m, HIDDEN, 0);
}

__global__ void __launch_bounds__(256, 2) k_mma_fc1(
    const float* __restrict__ w, const float* __restrict__ b) {
    hmma_tile<true>(d_h, w, b, d_m, HIDDEN, 0);
}

// one-off transpose of all layer weights: d_Wt[l][n][k] = W[l][k][n]
__global__ void k_transpose_all(const float* __restrict__ W) {
    __shared__ float t[32][33];
    int l = blockIdx.x >> 4;
    int bx = blockIdx.x & 3, by = (blockIdx.x >> 2) & 3;
    int x = threadIdx.x & 31, y = threadIdx.x >> 5;
    const float* Wl = W + (size_t)l * HIDDEN * HIDDEN;
    float* Wtl = d_Wt + (size_t)l * HIDDEN * HIDDEN;
#pragma unroll
    for (int i = 0; i < 32; i += 8)
        t[y + i][x] = Wl[(size_t)(by * 32 + y + i) * 128 + bx * 32 + x];
    __syncthreads();
#pragma unroll
    for (int i = 0; i < 32; i += 8)
        Wtl[(size_t)(bx * 32 + y + i) * 128 + by * 32 + x] = t[x][y + i];
}

// ---------------- setup kernels ----------------
__global__ void k_init() {
    int i = blockIdx.x * blockDim.x + threadIdx.x;
    if (i < N_NODES) d_deg[i] = 0;
    if (i < NUM_GRAPHS * HIDDEN) d_pool[i] = 0.f;
    if (i < NUM_GRAPHS) d_cnt[i] = 0;
    if (i < HIDDEN) { d_sum[i] = 0.f; d_sumsq[i] = 0.f; }
}

__global__ void k_copy_x(const float* __restrict__ x) {
    int i = blockIdx.x * blockDim.x + threadIdx.x;
    ((float4*)d_h)[i] = ((const float4*)x)[i];
}

__global__ void k_edges(const int* __restrict__ e) {
    int i = blockIdx.x * blockDim.x + threadIdx.x;
    int s = e[i];
    int d = e[N_EDGES + i];
    d_src[i] = s;
    d_dst[i] = d;
    atomicAdd(&d_deg[d], 1);
}

__global__ void k_batch_hist(const int* __restrict__ batch) {
    __shared__ int hc[NUM_GRAPHS];
    for (int i = threadIdx.x; i < NUM_GRAPHS; i += blockDim.x) hc[i] = 0;
    __syncthreads();
    int idx = blockIdx.x * blockDim.x + threadIdx.x;
    if (idx < N_NODES) atomicAdd(&hc[batch[idx]], 1);
    __syncthreads();
    for (int i = threadIdx.x; i < NUM_GRAPHS; i += blockDim.x)
        if (hc[i]) atomicAdd(&d_cnt[i], hc[i]);
}

// 3-phase parallel scan of d_deg -> d_rowptr / d_cursor
__global__ void k_scan1() {
    __shared__ int sh[32];
    int lane = threadIdx.x & 31, warp = threadIdx.x >> 5;
    int idx = blockIdx.x * 1024 + threadIdx.x;
    int v = (idx < N_NODES) ? d_deg[idx] : 0;
#pragma unroll
    for (int o = 16; o; o >>= 1) v += __shfl_down_sync(0xFFFFFFFFu, v, o);
    if (lane == 0) sh[warp] = v;
    __syncthreads();
    if (warp == 0) {
        v = sh[lane];
#pragma unroll
        for (int o = 16; o; o >>= 1) v += __shfl_down_sync(0xFFFFFFFFu, v, o);
        if (lane == 0) d_blocksum[blockIdx.x] = v;
    }
}

__global__ void k_scan2() {
    __shared__ int s[128];
    int t = threadIdx.x;
    int v = (t < 98) ? d_blocksum[t] : 0;
    s[t] = v;
    __syncthreads();
#pragma unroll
    for (int o = 1; o < 128; o <<= 1) {
        int tmp = (t >= o) ? s[t - o] : 0;
        __syncthreads();
        s[t] += tmp;
        __syncthreads();
    }
    if (t < 98) d_blockoff[t] = s[t] - v;
    if (t == 0) d_rowptr[N_NODES] = s[97];
}

__global__ void k_scan3() {
    __shared__ int s[1024];
    int t = threadIdx.x;
    int idx = blockIdx.x * 1024 + t;
    int v = (idx < N_NODES) ? d_deg[idx] : 0;
    s[t] = v;
    __syncthreads();
#pragma unroll
    for (int o = 1; o < 1024; o <<= 1) {
        int tmp = (t >= o) ? s[t - o] : 0;
        __syncthreads();
        s[t] += tmp;
        __syncthreads();
    }
    if (idx < N_NODES) {
        int ex = d_blockoff[blockIdx.x] + s[t] - v;
        d_rowptr[idx] = ex;
        d_cursor[idx] = ex;
    }
}

__global__ void k_csr_fill() {
    int i = blockIdx.x * blockDim.x + threadIdx.x;
    int pos = atomicAdd(&d_cursor[d_dst[i]], 1);
    d_colidx[pos] = d_src[i];
}

// ---------------- CSR aggregate: one warp per destination node ----------------
__global__ void k_aggregate() {
    int warp = (blockIdx.x * blockDim.x + threadIdx.x) >> 5;
    int lane = threadIdx.x & 31;
    if (warp >= N_NODES) return;
    int beg = d_rowptr[warp], end = d_rowptr[warp + 1];
    float4 acc = make_float4(0.f, 0.f, 0.f, 0.f);
    for (int e = beg; e < end; e++) {
        int src = d_colidx[e];
        float4 v = *(const float4*)(d_m + (size_t)src * HIDDEN + lane * 4);
        acc.x += v.x; acc.y += v.y; acc.z += v.z; acc.w += v.w;
    }
    *(float4*)(d_agg + (size_t)warp * HIDDEN + lane * 4) = acc;
}

// ---------------- batchnorm + relu + mean pool + classifier ----------------
__global__ void k_bn_stats() {
    int c = threadIdx.x;
    int n0 = blockIdx.x * 500;
    int n1 = n0 + 500;
    float s = 0.f, s2 = 0.f;
    for (int n = n0; n < n1; n++) {
        float v = d_m[(size_t)n * HIDDEN + c];
        s += v;
        s2 += v * v;
    }
    atomicAdd(&d_sum[c], s);
    atomicAdd(&d_sumsq[c], s2);
}

__global__ void k_bn_final() {
    int c = threadIdx.x;
    float mu = d_sum[c] / (float)N_NODES;
    float var = d_sumsq[c] / (float)N_NODES - mu * mu;
    d_mean[c] = mu;
    d_rstd[c] = rsqrtf(var + BN_EPS);
}

__global__ void k_pool(const int* __restrict__ batch,
                       const float* __restrict__ gamma,
                       const float* __restrict__ beta) {
    int c = threadIdx.x;
    int n0 = blockIdx.x * 512;
    int n1 = n0 + 512;
    if (n1 > N_NODES) n1 = N_NODES;
    if (n0 >= N_NODES) return;
    float sc = gamma[c] * d_rstd[c];
    float mu = d_mean[c];
    float be = beta[c];
    float acc = 0.f;
    int cur = batch[n0];
    for (int n = n0; n < n1; n++) {
        int bb = batch[n];
        if (bb != cur) {
            atomicAdd(&d_pool[cur * HIDDEN + c], acc);
            acc = 0.f;
            cur = bb;
        }
        float v = (d_m[(size_t)n * HIDDEN + c] - mu) * sc + be;
        acc += fmaxf(v, 0.f);
    }
    atomicAdd(&d_pool[cur * HIDDEN + c], acc);
}

__global__ void k_final(const float* __restrict__ w2, const float* __restrict__ b2,
                        float* __restrict__ out) {
    __shared__ float sf[HIDDEN];
    __shared__ float lg[NUM_CLASSES];
    int g = blockIdx.x, t = threadIdx.x;
    float cnt = fmaxf((float)d_cnt[g], 1.f);
    sf[t] = d_pool[g * HIDDEN + t] / cnt;
    __syncthreads();
    if (t < NUM_CLASSES) {
        float s = b2[t];
        for (int k = 0; k < HIDDEN; k++) s += sf[k] * w2[t * HIDDEN + k];
        lg[t] = s;
    }
    __syncthreads();
    if (t == 0) {
        float mx = -1e30f;
        for (int c = 0; c < NUM_CLASSES; c++) mx = fmaxf(mx, lg[c]);
        float se = 0.f;
        for (int c = 0; c < NUM_CLASSES; c++) se += expf(lg[c] - mx);
        float lse = mx + logf(se);
        for (int c = 0; c < NUM_CLASSES; c++) out[g * NUM_CLASSES + c] = lg[c] - lse;
    }
}

// ---------------- launch ----------------
extern "C" void kernel_launch(void* const* d_in, const int* in_sizes, int n_in,
                              void* d_out, int out_size) {
    const float* x     = (const float*)d_in[0];
    const int*   ei    = (const int*)d_in[1];
    const int*   bat   = (const int*)d_in[2];
    const float* ggnn  = (const float*)d_in[3];
    const float* wih   = (const float*)d_in[4];
    const float* whh   = (const float*)d_in[5];
    const float* bih   = (const float*)d_in[6];
    const float* bhh   = (const float*)d_in[7];
    const float* fc1w  = (const float*)d_in[8];
    const float* fc1b  = (const float*)d_in[9];
    const float* gamma = (const float*)d_in[10];
    const float* beta  = (const float*)d_in[11];
    const float* fc2w  = (const float*)d_in[12];
    const float* fc2b  = (const float*)d_in[13];
    float* out = (float*)d_out;

    cudaFuncSetAttribute(k_gru_fused, cudaFuncAttributeMaxDynamicSharedMemorySize,
                         GRU_SMEM_BYTES);

    k_init<<<(N_NODES + 255) / 256, 256>>>();
    k_copy_x<<<(N_NODES * HIDDEN / 4) / 256, 256>>>(x);
    k_edges<<<N_EDGES / 256, 256>>>(ei);
    k_batch_hist<<<98, 1024>>>(bat);
    k_scan1<<<98, 1024>>>();
    k_scan2<<<1, 128>>>();
    k_scan3<<<98, 1024>>>();
    k_csr_fill<<<N_EDGES / 256, 256>>>();
    k_transpose_all<<<64, 256>>>(ggnn);

    const int gb = (N_NODES + 127) / 128;  // 782
    for (int l = 0; l < NUM_LAYERS; l++) {
        k_mma_msg<<<gb, 256>>>(l);
        k_aggregate<<<(N_NODES * 32) / 256, 256>>>();
        k_gru_fused<<<gb, 512, GRU_SMEM_BYTES>>>(wih, whh, bih, bhh);
    }

    k_mma_fc1<<<gb, 256>>>(fc1w, fc1b);
    k_bn_stats<<<200, 128>>>();
    k_bn_final<<<1, 128>>>();
    k_pool<<<(N_NODES + 511) / 512, 128>>>(bat, gamma, beta);
    k_final<<<NUM_GRAPHS, 128>>>(fc2w, fc2b, out);
}

// round 7
// speedup vs baseline: 2.4264x; 1.0248x over previous
#include <cuda_runtime.h>
#include <cstdint>

#define N_NODES 100000
#define N_EDGES 1600000
#define HIDDEN 128
#define NUM_CLASSES 10
#define NUM_LAYERS 4
#define NUM_GRAPHS 200
#define BN_EPS 1e-5f

// ---------------- scratch (static device arrays: no allocations) ----------------
__device__ float d_h[(size_t)N_NODES * HIDDEN];
__device__ float d_m[(size_t)N_NODES * HIDDEN];       // fc1 output
__device__ float d_agg[(size_t)N_NODES * HIDDEN];     // hsum (gathered h)
__device__ float d_Wcomb[NUM_LAYERS * 3 * HIDDEN * HIDDEN];  // Wih @ W_l^T per layer
__device__ int d_src[N_EDGES];
__device__ int d_dst[N_EDGES];
__device__ int d_deg[N_NODES];
__device__ int d_rowptr[N_NODES + 1];
__device__ int d_cursor[N_NODES];
__device__ int d_colidx[N_EDGES];
__device__ int d_blocksum[128];
__device__ int d_blockoff[128];
__device__ float d_sum[HIDDEN], d_sumsq[HIDDEN], d_mean[HIDDEN], d_rstd[HIDDEN];
__device__ float d_pool[NUM_GRAPHS * HIDDEN];
__device__ int d_cnt[NUM_GRAPHS];

// ---------------- helpers ----------------
__device__ __forceinline__ float sigm_f(float x) {
    return __fdividef(1.f, 1.f + __expf(-x));
}
__device__ __forceinline__ float tanh_f(float x) {
    return 1.f - __fdividef(2.f, __expf(2.f * x) + 1.f);
}
__device__ __forceinline__ uint32_t smem_u32(const void* p) {
    uint32_t a;
    asm("{ .reg .u64 t; cvta.to.shared.u64 t, %1; cvt.u32.u64 %0, t; }" : "=r"(a) : "l"(p));
    return a;
}
__device__ __forceinline__ uint32_t f2tf32(float f) {
    uint32_t r;
    asm("cvt.rna.tf32.f32 %0, %1;" : "=r"(r) : "f"(f));
    return r;
}
__device__ __forceinline__ void mma_tf32(float* c, const uint32_t* a, const uint32_t* b) {
    asm volatile(
        "mma.sync.aligned.m16n8k8.row.col.f32.tf32.tf32.f32 "
        "{%0,%1,%2,%3}, {%4,%5,%6,%7}, {%8,%9}, {%0,%1,%2,%3};"
        : "+f"(c[0]), "+f"(c[1]), "+f"(c[2]), "+f"(c[3])
        : "r"(a[0]), "r"(a[1]), "r"(a[2]), "r"(a[3]), "r"(b[0]), "r"(b[1]));
}
__device__ __forceinline__ void cpasync16(uint32_t daddr, const void* src, int srcbytes) {
    asm volatile("cp.async.cg.shared.global [%0], [%1], 16, %2;"
                 :: "r"(daddr), "l"(src), "r"(srcbytes));
}
__device__ __forceinline__ void cpasync_commit() {
    asm volatile("cp.async.commit_group;" ::: "memory");
}

#define ASTRIDE 36
#define GRU_AS_W (64 * 260)   // A tile [64 rows][256 k + 4 pad] words
#define GRU_BS_W (128 * 36)   // weight chunk [128 n][32 k + 4 pad] words
#define GRU_SMEM_BYTES ((GRU_AS_W + 2 * GRU_BS_W) * 4)  // 103424 B

// ============ fused GRU layer v2: 64 rows/block, 512 thr, cp.async pipeline ============
// Gate g: out = hsum @ Wcomb_g^T + h @ Whh_g^T (K=256, 8 chunks of 32).
// Pass order: R(g=0) -> N(g=2) -> Z(g=1). rr/nn register-resident.
__device__ __forceinline__ void gru_issueB(
    uint32_t bsaddr, const float* __restrict__ wcomb, const float* __restrict__ whh,
    int j, int tid)
{
    int pass = j >> 3;
    int g = (pass == 0) ? 0 : (pass == 1) ? 2 : 1;
    int cc = j & 7;
    const float* base = ((cc < 4) ? wcomb : whh) + (size_t)g * 128 * HIDDEN + (cc & 3) * 32;
#pragma unroll
    for (int q = tid; q < 1024; q += 512) {
        int nr = q >> 3, k4 = (q & 7) << 2;
        cpasync16(bsaddr + (nr * ASTRIDE + k4) * 4, base + (size_t)nr * HIDDEN + k4, 16);
    }
    cpasync_commit();
}

__device__ __forceinline__ void gru_chunk_mma(
    const uint32_t* __restrict__ AS, const uint32_t* __restrict__ BS,
    float (&acc)[4][4], int abase, int lr1, int lr2, int wn, int gid, int tg)
{
#pragma unroll
    for (int ks = 0; ks < 4; ks++) {
        int k0 = ks * 8;
        uint32_t af[4];
        af[0] = AS[lr1 * 260 + abase + k0 + tg];
        af[1] = AS[lr2 * 260 + abase + k0 + tg];
        af[2] = AS[lr1 * 260 + abase + k0 + tg + 4];
        af[3] = AS[lr2 * 260 + abase + k0 + tg + 4];
#pragma unroll
        for (int nt = 0; nt < 4; nt++) {
            uint32_t bf[2];
            int nb = wn * 32 + nt * 8 + gid;
            bf[0] = BS[nb * ASTRIDE + k0 + tg];
            bf[1] = BS[nb * ASTRIDE + k0 + tg + 4];
            mma_tf32(acc[nt], af, bf);
        }
    }
}

__global__ void __launch_bounds__(512, 1) k_gru_fused(
    int layer, const float* __restrict__ whh,
    const float* __restrict__ bih, const float* __restrict__ bhh)
{
    extern __shared__ uint32_t dsm[];
    const float* wcomb = d_Wcomb + (size_t)layer * 3 * HIDDEN * HIDDEN;
    const uint32_t sb = smem_u32(dsm);
    const uint32_t sbBS0 = sb + GRU_AS_W * 4;

    const int tid = threadIdx.x, lane = tid & 31, w = tid >> 5;
    const int wm = w & 3, wn = w >> 2;  // 4 m-strips x 4 n-strips
    const int gid = lane >> 2, tg = lane & 3;
    const int row0 = blockIdx.x * 64;
    const int lr1 = wm * 16 + gid, lr2 = lr1 + 8;

    // ---- prologue: A tile + chunk0 (G0), chunk1 (G1) ----
#pragma unroll
    for (int q = tid; q < 4096; q += 512) {
        int r = q >> 6, c4 = (q & 63) << 2;
        int gr = row0 + r;
        int ok = (gr < N_NODES);
        if (!ok) gr = 0;
        const float* src = (c4 < 128) ? d_agg + (size_t)gr * HIDDEN + c4
                                      : d_h + (size_t)gr * HIDDEN + (c4 - 128);
        cpasync16(sb + (r * 260 + c4) * 4, src, ok ? 16 : 0);
    }
    gru_issueB(sbBS0, wcomb, whh, 0, tid);                 // G0 (with A)
    gru_issueB(sbBS0 + GRU_BS_W * 4, wcomb, whh, 1, tid);  // G1

    float rr[4][4], nn[4][4], ci[4][4], ch[4][4];
#pragma unroll
    for (int j = 0; j < 4; j++)
#pragma unroll
        for (int q = 0; q < 4; q++) { ci[j][q] = 0.f; ch[j][q] = 0.f; }

    for (int it = 0; it < 24; it++) {
        int pass = it >> 3, cc = it & 7;
        if (it < 22) asm volatile("cp.async.wait_group 1;" ::: "memory");
        else asm volatile("cp.async.wait_group 0;" ::: "memory");
        __syncthreads();

        const uint32_t* BS = dsm + GRU_AS_W + (it & 1) * GRU_BS_W;
        if (pass == 1 && cc >= 4)
            gru_chunk_mma(dsm, BS, ch, cc * 32, lr1, lr2, wn, gid, tg);
        else
            gru_chunk_mma(dsm, BS, ci, cc * 32, lr1, lr2, wn, gid, tg);

        if (cc == 7) {
            if (pass == 0) {  // R epilogue
#pragma unroll
                for (int nt = 0; nt < 4; nt++) {
                    int coli = wn * 32 + nt * 8 + tg * 2;
                    float b0 = bih[coli] + bhh[coli];
                    float b1 = bih[coli + 1] + bhh[coli + 1];
                    rr[nt][0] = sigm_f(ci[nt][0] + b0);
                    rr[nt][1] = sigm_f(ci[nt][1] + b1);
                    rr[nt][2] = sigm_f(ci[nt][2] + b0);
                    rr[nt][3] = sigm_f(ci[nt][3] + b1);
#pragma unroll
                    for (int q = 0; q < 4; q++) ci[nt][q] = 0.f;
                }
            } else if (pass == 1) {  // N epilogue
#pragma unroll
                for (int nt = 0; nt < 4; nt++) {
                    int coli = wn * 32 + nt * 8 + tg * 2;
                    float bi0 = bih[256 + coli], bi1 = bih[256 + coli + 1];
                    float bh0 = bhh[256 + coli], bh1 = bhh[256 + coli + 1];
                    nn[nt][0] = tanh_f(ci[nt][0] + bi0 + rr[nt][0] * (ch[nt][0] + bh0));
                    nn[nt][1] = tanh_f(ci[nt][1] + bi1 + rr[nt][1] * (ch[nt][1] + bh1));
                    nn[nt][2] = tanh_f(ci[nt][2] + bi0 + rr[nt][2] * (ch[nt][2] + bh0));
                    nn[nt][3] = tanh_f(ci[nt][3] + bi1 + rr[nt][3] * (ch[nt][3] + bh1));
#pragma unroll
                    for (int q = 0; q < 4; q++) ci[nt][q] = 0.f;
                }
            } else {  // Z epilogue + in-place h update
                int gr1 = row0 + lr1, gr2 = row0 + lr2;
#pragma unroll
                for (int nt = 0; nt < 4; nt++) {
                    int coli = wn * 32 + nt * 8 + tg * 2;
                    float b0 = bih[128 + coli] + bhh[128 + coli];
                    float b1 = bih[128 + coli + 1] + bhh[128 + coli + 1];
                    if (gr1 < N_NODES) {
                        float* hp = d_h + (size_t)gr1 * HIDDEN + coli;
                        float2 h = *(float2*)hp;
                        float z0 = sigm_f(ci[nt][0] + b0), z1 = sigm_f(ci[nt][1] + b1);
                        float2 o;
                        o.x = (1.f - z0) * nn[nt][0] + z0 * h.x;
                        o.y = (1.f - z1) * nn[nt][1] + z1 * h.y;
                        *(float2*)hp = o;
                    }
                    if (gr2 < N_NODES) {
                        float* hp = d_h + (size_t)gr2 * HIDDEN + coli;
                        float2 h = *(float2*)hp;
                        float z0 = sigm_f(ci[nt][2] + b0), z1 = sigm_f(ci[nt][3] + b1);
                        float2 o;
                        o.x = (1.f - z0) * nn[nt][2] + z0 * h.x;
                        o.y = (1.f - z1) * nn[nt][3] + z1 * h.y;
                        *(float2*)hp = o;
                    }
                }
            }
        }
        __syncthreads();
        if (it + 2 < 24)
            gru_issueB(sbBS0 + (it & 1) * GRU_BS_W * 4, wcomb, whh, it + 2, tid);
    }
}

// ---------------- Wcomb precompute (fp32): d_Wcomb[l][g*128+n][k] = sum_j wih[g*128+n][j]*ggnn[l][k][j]
__global__ void __launch_bounds__(256) k_wcomb(const float* __restrict__ wih,
                                               const float* __restrict__ ggnn) {
    __shared__ float As[16][128];
    __shared__ float Bs[16][128];
    const float* A = wih + (size_t)blockIdx.x * 128 * HIDDEN;           // gate rows
    const float* B = ggnn + (size_t)blockIdx.y * HIDDEN * HIDDEN;       // layer
    float* C = d_Wcomb + ((size_t)blockIdx.y * 3 + blockIdx.x) * 128 * HIDDEN;
    const int tid = threadIdx.x, tx = tid & 15, ty = tid >> 4;

    float acc[8][8];
#pragma unroll
    for (int i = 0; i < 8; i++)
#pragma unroll
        for (int j = 0; j < 8; j++) acc[i][j] = 0.f;

    for (int j0 = 0; j0 < 128; j0 += 16) {
#pragma unroll
        for (int q = tid; q < 512; q += 256) {
            int n = q >> 2, j4 = (q & 3) << 2;
            float4 va = *(const float4*)(A + (size_t)n * HIDDEN + j0 + j4);
            As[j4 + 0][n] = va.x; As[j4 + 1][n] = va.y;
            As[j4 + 2][n] = va.z; As[j4 + 3][n] = va.w;
            float4 vb = *(const float4*)(B + (size_t)n * HIDDEN + j0 + j4);
            Bs[j4 + 0][n] = vb.x; Bs[j4 + 1][n] = vb.y;
            Bs[j4 + 2][n] = vb.z; Bs[j4 + 3][n] = vb.w;
        }
        __syncthreads();
#pragma unroll
        for (int jj = 0; jj < 16; jj++) {
            float a[8], b[8];
#pragma unroll
            for (int i = 0; i < 8; i++) a[i] = As[jj][ty * 8 + i];
#pragma unroll
            for (int j = 0; j < 8; j++) b[j] = Bs[jj][tx * 8 + j];
#pragma unroll
            for (int i = 0; i < 8; i++)
#pragma unroll
                for (int j = 0; j < 8; j++) acc[i][j] = fmaf(a[i], b[j], acc[i][j]);
        }
        __syncthreads();
    }
#pragma unroll
    for (int i = 0; i < 8; i++)
#pragma unroll
        for (int j = 0; j < 8; j++)
            C[(size_t)(ty * 8 + i) * HIDDEN + tx * 8 + j] = acc[i][j];
}

// ---------------- HMMA tf32 GEMM tile (fc1), 256 thr, occ 2 ----------------
template <bool HASBIAS>
__device__ __forceinline__ void hmma_tile(
    const float* __restrict__ A, const float* __restrict__ Bt,
    const float* __restrict__ bias, float* __restrict__ C, int ldc, int ccol0)
{
    __shared__ uint32_t As[128 * ASTRIDE];
    __shared__ uint32_t Bs[128 * ASTRIDE];
    const int tid = threadIdx.x, lane = tid & 31, w = tid >> 5;
    const int wm = w & 3, wn = w >> 2;
    const int gid = lane >> 2, tg = lane & 3;
    const int row0 = blockIdx.x * 128;

    float c[2][8][4];
#pragma unroll
    for (int i = 0; i < 2; i++)
#pragma unroll
        for (int j = 0; j < 8; j++)
#pragma unroll
            for (int q = 0; q < 4; q++) c[i][j][q] = 0.f;

#pragma unroll
    for (int kp = 0; kp < 4; kp++) {
        if (kp) __syncthreads();
#pragma unroll
        for (int q = tid; q < 1024; q += 256) {
            int r = q >> 3, k4 = (q & 7) << 2;
            int gr = row0 + r;
            if (gr >= N_NODES) gr = N_NODES - 1;
            float4 va = *(const float4*)(A + (size_t)gr * HIDDEN + kp * 32 + k4);
            *(uint4*)(As + r * ASTRIDE + k4) =
                make_uint4(f2tf32(va.x), f2tf32(va.y), f2tf32(va.z), f2tf32(va.w));
            float4 vb = *(const float4*)(Bt + (size_t)r * HIDDEN + kp * 32 + k4);
            *(uint4*)(Bs + r * ASTRIDE + k4) =
                make_uint4(f2tf32(vb.x), f2tf32(vb.y), f2tf32(vb.z), f2tf32(vb.w));
        }
        __syncthreads();
#pragma unroll
        for (int ks = 0; ks < 4; ks++) {
            int k0 = ks * 8;
            uint32_t af[2][4];
#pragma unroll
            for (int mt = 0; mt < 2; mt++) {
                int rb = wm * 32 + mt * 16;
                af[mt][0] = As[(rb + gid) * ASTRIDE + k0 + tg];
                af[mt][1] = As[(rb + gid + 8) * ASTRIDE + k0 + tg];
                af[mt][2] = As[(rb + gid) * ASTRIDE + k0 + tg + 4];
                af[mt][3] = As[(rb + gid + 8) * ASTRIDE + k0 + tg + 4];
            }
#pragma unroll
            for (int nt = 0; nt < 8; nt++) {
                uint32_t bf[2];
                int nb = wn * 64 + nt * 8 + gid;
                bf[0] = Bs[nb * ASTRIDE + k0 + tg];
                bf[1] = Bs[nb * ASTRIDE + k0 + tg + 4];
#pragma unroll
                for (int mt = 0; mt < 2; mt++) mma_tf32(c[mt][nt], af[mt], bf);
            }
        }
    }

#pragma unroll
    for (int mt = 0; mt < 2; mt++) {
        int r1 = row0 + wm * 32 + mt * 16 + gid;
        int r2 = r1 + 8;
#pragma unroll
        for (int nt = 0; nt < 8; nt++) {
            int coli = wn * 64 + nt * 8 + tg * 2;
            float b0 = 0.f, b1 = 0.f;
            if (HASBIAS) { b0 = bias[coli]; b1 = bias[coli + 1]; }
            if (r1 < N_NODES) {
                float2 v = make_float2(c[mt][nt][0] + b0, c[mt][nt][1] + b1);
                *(float2*)(C + (size_t)r1 * ldc + ccol0 + coli) = v;
            }
            if (r2 < N_NODES) {
                float2 v = make_float2(c[mt][nt][2] + b0, c[mt][nt][3] + b1);
                *(float2*)(C + (size_t)r2 * ldc + ccol0 + coli) = v;
            }
        }
    }
}

__global__ void __launch_bounds__(256, 2) k_mma_fc1(
    const float* __restrict__ w, const float* __restrict__ b) {
    hmma_tile<true>(d_h, w, b, d_m, HIDDEN, 0);
}

// ---------------- setup kernels ----------------
__global__ void k_init() {
    int i = blockIdx.x * blockDim.x + threadIdx.x;
    if (i < N_NODES) d_deg[i] = 0;
    if (i < NUM_GRAPHS * HIDDEN) d_pool[i] = 0.f;
    if (i < NUM_GRAPHS) d_cnt[i] = 0;
    if (i < HIDDEN) { d_sum[i] = 0.f; d_sumsq[i] = 0.f; }
}

__global__ void k_copy_x(const float* __restrict__ x) {
    int i = blockIdx.x * blockDim.x + threadIdx.x;
    ((float4*)d_h)[i] = ((const float4*)x)[i];
}

__global__ void k_edges(const int* __restrict__ e) {
    int i = blockIdx.x * blockDim.x + threadIdx.x;
    int s = e[i];
    int d = e[N_EDGES + i];
    d_src[i] = s;
    d_dst[i] = d;
    atomicAdd(&d_deg[d], 1);
}

__global__ void k_batch_hist(const int* __restrict__ batch) {
    __shared__ int hc[NUM_GRAPHS];
    for (int i = threadIdx.x; i < NUM_GRAPHS; i += blockDim.x) hc[i] = 0;
    __syncthreads();
    int idx = blockIdx.x * blockDim.x + threadIdx.x;
    if (idx < N_NODES) atomicAdd(&hc[batch[idx]], 1);
    __syncthreads();
    for (int i = threadIdx.x; i < NUM_GRAPHS; i += blockDim.x)
        if (hc[i]) atomicAdd(&d_cnt[i], hc[i]);
}

// 3-phase parallel scan of d_deg -> d_rowptr / d_cursor
__global__ void k_scan1() {
    __shared__ int sh[32];
    int lane = threadIdx.x & 31, warp = threadIdx.x >> 5;
    int idx = blockIdx.x * 1024 + threadIdx.x;
    int v = (idx < N_NODES) ? d_deg[idx] : 0;
#pragma unroll
    for (int o = 16; o; o >>= 1) v += __shfl_down_sync(0xFFFFFFFFu, v, o);
    if (lane == 0) sh[warp] = v;
    __syncthreads();
    if (warp == 0) {
        v = sh[lane];
#pragma unroll
        for (int o = 16; o; o >>= 1) v += __shfl_down_sync(0xFFFFFFFFu, v, o);
        if (lane == 0) d_blocksum[blockIdx.x] = v;
    }
}

__global__ void k_scan2() {
    __shared__ int s[128];
    int t = threadIdx.x;
    int v = (t < 98) ? d_blocksum[t] : 0;
    s[t] = v;
    __syncthreads();
#pragma unroll
    for (int o = 1; o < 128; o <<= 1) {
        int tmp = (t >= o) ? s[t - o] : 0;
        __syncthreads();
        s[t] += tmp;
        __syncthreads();
    }
    if (t < 98) d_blockoff[t] = s[t] - v;
    if (t == 0) d_rowptr[N_NODES] = s[97];
}

__global__ void k_scan3() {
    __shared__ int s[1024];
    int t = threadIdx.x;
    int idx = blockIdx.x * 1024 + t;
    int v = (idx < N_NODES) ? d_deg[idx] : 0;
    s[t] = v;
    __syncthreads();
#pragma unroll
    for (int o = 1; o < 1024; o <<= 1) {
        int tmp = (t >= o) ? s[t - o] : 0;
        __syncthreads();
        s[t] += tmp;
        __syncthreads();
    }
    if (idx < N_NODES) {
        int ex = d_blockoff[blockIdx.x] + s[t] - v;
        d_rowptr[idx] = ex;
        d_cursor[idx] = ex;
    }
}

__global__ void k_csr_fill() {
    int i = blockIdx.x * blockDim.x + threadIdx.x;
    int pos = atomicAdd(&d_cursor[d_dst[i]], 1);
    d_colidx[pos] = d_src[i];
}

// ---------------- CSR aggregate of h: one warp per destination node ----------------
__global__ void k_aggregate() {
    int warp = (blockIdx.x * blockDim.x + threadIdx.x) >> 5;
    int lane = threadIdx.x & 31;
    if (warp >= N_NODES) return;
    int beg = d_rowptr[warp], end = d_rowptr[warp + 1];
    float4 acc = make_float4(0.f, 0.f, 0.f, 0.f);
    for (int e = beg; e < end; e++) {
        int src = d_colidx[e];
        float4 v = *(const float4*)(d_h + (size_t)src * HIDDEN + lane * 4);
        acc.x += v.x; acc.y += v.y; acc.z += v.z; acc.w += v.w;
    }
    *(float4*)(d_agg + (size_t)warp * HIDDEN + lane * 4) = acc;
}

// ---------------- batchnorm + relu + mean pool + classifier ----------------
__global__ void k_bn_stats() {
    int c = threadIdx.x;
    int n0 = blockIdx.x * 500;
    int n1 = n0 + 500;
    float s = 0.f, s2 = 0.f;
    for (int n = n0; n < n1; n++) {
        float v = d_m[(size_t)n * HIDDEN + c];
        s += v;
        s2 += v * v;
    }
    atomicAdd(&d_sum[c], s);
    atomicAdd(&d_sumsq[c], s2);
}

__global__ void k_bn_final() {
    int c = threadIdx.x;
    float mu = d_sum[c] / (float)N_NODES;
    float var = d_sumsq[c] / (float)N_NODES - mu * mu;
    d_mean[c] = mu;
    d_rstd[c] = rsqrtf(var + BN_EPS);
}

__global__ void k_pool(const int* __restrict__ batch,
                       const float* __restrict__ gamma,
                       const float* __restrict__ beta) {
    int c = threadIdx.x;
    int n0 = blockIdx.x * 512;
    int n1 = n0 + 512;
    if (n1 > N_NODES) n1 = N_NODES;
    if (n0 >= N_NODES) return;
    float sc = gamma[c] * d_rstd[c];
    float mu = d_mean[c];
    float be = beta[c];
    float acc = 0.f;
    int cur = batch[n0];
    for (int n = n0; n < n1; n++) {
        int bb = batch[n];
        if (bb != cur) {
            atomicAdd(&d_pool[cur * HIDDEN + c], acc);
            acc = 0.f;
            cur = bb;
        }
        float v = (d_m[(size_t)n * HIDDEN + c] - mu) * sc + be;
        acc += fmaxf(v, 0.f);
    }
    atomicAdd(&d_pool[cur * HIDDEN + c], acc);
}

__global__ void k_final(const float* __restrict__ w2, const float* __restrict__ b2,
                        float* __restrict__ out) {
    __shared__ float sf[HIDDEN];
    __shared__ float lg[NUM_CLASSES];
    int g = blockIdx.x, t = threadIdx.x;
    float cnt = fmaxf((float)d_cnt[g], 1.f);
    sf[t] = d_pool[g * HIDDEN + t] / cnt;
    __syncthreads();
    if (t < NUM_CLASSES) {
        float s = b2[t];
        for (int k = 0; k < HIDDEN; k++) s += sf[k] * w2[t * HIDDEN + k];
        lg[t] = s;
    }
    __syncthreads();
    if (t == 0) {
        float mx = -1e30f;
        for (int c = 0; c < NUM_CLASSES; c++) mx = fmaxf(mx, lg[c]);
        float se = 0.f;
        for (int c = 0; c < NUM_CLASSES; c++) se += expf(lg[c] - mx);
        float lse = mx + logf(se);
        for (int c = 0; c < NUM_CLASSES; c++) out[g * NUM_CLASSES + c] = lg[c] - lse;
    }
}

// ---------------- launch ----------------
extern "C" void kernel_launch(void* const* d_in, const int* in_sizes, int n_in,
                              void* d_out, int out_size) {
    const float* x     = (const float*)d_in[0];
    const int*   ei    = (const int*)d_in[1];
    const int*   bat   = (const int*)d_in[2];
    const float* ggnn  = (const float*)d_in[3];
    const float* wih   = (const float*)d_in[4];
    const float* whh   = (const float*)d_in[5];
    const float* bih   = (const float*)d_in[6];
    const float* bhh   = (const float*)d_in[7];
    const float* fc1w  = (const float*)d_in[8];
    const float* fc1b  = (const float*)d_in[9];
    const float* gamma = (const float*)d_in[10];
    const float* beta  = (const float*)d_in[11];
    const float* fc2w  = (const float*)d_in[12];
    const float* fc2b  = (const float*)d_in[13];
    float* out = (float*)d_out;

    cudaFuncSetAttribute(k_gru_fused, cudaFuncAttributeMaxDynamicSharedMemorySize,
                         GRU_SMEM_BYTES);

    k_init<<<(N_NODES + 255) / 256, 256>>>();
    k_copy_x<<<(N_NODES * HIDDEN / 4) / 256, 256>>>(x);
    k_edges<<<N_EDGES / 256, 256>>>(ei);
    k_batch_hist<<<98, 1024>>>(bat);
    k_scan1<<<98, 1024>>>();
    k_scan2<<<1, 128>>>();
    k_scan3<<<98, 1024>>>();
    k_csr_fill<<<N_EDGES / 256, 256>>>();
    k_wcomb<<<dim3(3, NUM_LAYERS), 256>>>(wih, ggnn);

    const int gru_blocks = (N_NODES + 63) / 64;  // 1563
    for (int l = 0; l < NUM_LAYERS; l++) {
        k_aggregate<<<(N_NODES * 32) / 256, 256>>>();
        k_gru_fused<<<gru_blocks, 512, GRU_SMEM_BYTES>>>(l, whh, bih, bhh);
    }

    k_mma_fc1<<<(N_NODES + 127) / 128, 256>>>(fc1w, fc1b);
    k_bn_stats<<<200, 128>>>();
    k_bn_final<<<1, 128>>>();
    k_pool<<<(N_NODES + 511) / 512, 128>>>(bat, gamma, beta);
    k_final<<<NUM_GRAPHS, 128>>>(fc2w, fc2b, out);
}

// round 8
// speedup vs baseline: 2.6843x; 1.1063x over previous
#include <cuda_runtime.h>
#include <cuda_bf16.h>
#include <cstdint>

#define N_NODES 100000
#define N_EDGES 1600000
#define HIDDEN 128
#define NUM_CLASSES 10
#define NUM_LAYERS 4
#define NUM_GRAPHS 200
#define BN_EPS 1e-5f

// ---------------- scratch (static device arrays: no allocations) ----------------
__device__ float d_h[(size_t)N_NODES * HIDDEN];            // exact fp32 state
__device__ __nv_bfloat16 d_h_bf[(size_t)N_NODES * HIDDEN]; // bf16 mirror (gather source)
__device__ __nv_bfloat16 d_agg_bf[(size_t)N_NODES * HIDDEN];
__device__ float d_m[(size_t)N_NODES * HIDDEN];            // fc1 output
__device__ __nv_bfloat16 d_Wcomb_bf[NUM_LAYERS * 3 * HIDDEN * HIDDEN];
__device__ __nv_bfloat16 d_whh_bf[3 * HIDDEN * HIDDEN];
__device__ int d_src[N_EDGES];
__device__ int d_dst[N_EDGES];
__device__ int d_deg[N_NODES];
__device__ int d_rowptr[N_NODES + 1];
__device__ int d_cursor[N_NODES];
__device__ int d_colidx[N_EDGES];
__device__ int d_blocksum[128];
__device__ int d_blockoff[128];
__device__ float d_sum[HIDDEN], d_sumsq[HIDDEN], d_mean[HIDDEN], d_rstd[HIDDEN];
__device__ float d_pool[NUM_GRAPHS * HIDDEN];
__device__ int d_cnt[NUM_GRAPHS];

// ---------------- helpers ----------------
__device__ __forceinline__ float sigm_f(float x) {
    return __fdividef(1.f, 1.f + __expf(-x));
}
__device__ __forceinline__ float tanh_f(float x) {
    return 1.f - __fdividef(2.f, __expf(2.f * x) + 1.f);
}
__device__ __forceinline__ uint32_t smem_u32(const void* p) {
    uint32_t a;
    asm("{ .reg .u64 t; cvta.to.shared.u64 t, %1; cvt.u32.u64 %0, t; }" : "=r"(a) : "l"(p));
    return a;
}
__device__ __forceinline__ uint32_t f2tf32(float f) {
    uint32_t r;
    asm("cvt.rna.tf32.f32 %0, %1;" : "=r"(r) : "f"(f));
    return r;
}
__device__ __forceinline__ uint32_t bf2(float lo, float hi) {
    __nv_bfloat162 p = __floats2bfloat162_rn(lo, hi);
    return *(uint32_t*)&p;
}
__device__ __forceinline__ void mma_tf32(float* c, const uint32_t* a, const uint32_t* b) {
    asm volatile(
        "mma.sync.aligned.m16n8k8.row.col.f32.tf32.tf32.f32 "
        "{%0,%1,%2,%3}, {%4,%5,%6,%7}, {%8,%9}, {%0,%1,%2,%3};"
        : "+f"(c[0]), "+f"(c[1]), "+f"(c[2]), "+f"(c[3])
        : "r"(a[0]), "r"(a[1]), "r"(a[2]), "r"(a[3]), "r"(b[0]), "r"(b[1]));
}
__device__ __forceinline__ void mma_bf16(float* c, const uint32_t* a, const uint32_t* b) {
    asm volatile(
        "mma.sync.aligned.m16n8k16.row.col.f32.bf16.bf16.f32 "
        "{%0,%1,%2,%3}, {%4,%5,%6,%7}, {%8,%9}, {%0,%1,%2,%3};"
        : "+f"(c[0]), "+f"(c[1]), "+f"(c[2]), "+f"(c[3])
        : "r"(a[0]), "r"(a[1]), "r"(a[2]), "r"(a[3]), "r"(b[0]), "r"(b[1]));
}
__device__ __forceinline__ void cpasync16(uint32_t daddr, const void* src, int srcbytes) {
    asm volatile("cp.async.cg.shared.global [%0], [%1], 16, %2;"
                 :: "r"(daddr), "l"(src), "r"(srcbytes));
}
__device__ __forceinline__ void cpasync_commit() {
    asm volatile("cp.async.commit_group;" ::: "memory");
}

#define ASTRIDE 36
// gru smem (uint32 words, each = one bf16x2): A [64 rows][132], B 3 x [128][36]
#define S2A 132
#define S2B 36
#define AS_W (64 * S2A)
#define BS_W (128 * S2B)
#define GRU_SMEM_BYTES ((AS_W + 3 * BS_W) * 4)  // 89088 B

// ============ fused GRU layer (bf16 MMA): 64 rows/block, 512 thr, 3-deep cp.async ============
// Gate g: out = hsum @ Wcomb_g^T + h @ Whh_g^T (K=256 = 4 chunks of 64 halves).
// 12 chunks total: pass R(g=0) cc0-3, N(g=2) cc4-7, Z(g=1) cc8-11.
__device__ __forceinline__ void gru_issueB(uint32_t bufaddr, const __nv_bfloat16* __restrict__ wcomb,
                                           int chunk, int tid) {
    int pass = chunk >> 2;
    int g = (pass == 0) ? 0 : (pass == 1) ? 2 : 1;
    int sub = chunk & 3;
    const __nv_bfloat16* base = ((sub < 2) ? wcomb : d_whh_bf) +
                                (size_t)g * 128 * HIDDEN + (sub & 1) * 64;
#pragma unroll
    for (int q = tid; q < 1024; q += 512) {
        int n = q >> 3, o = q & 7;  // 8 x 16B per 64-half row slice
        cpasync16(bufaddr + (n * S2B + o * 4) * 4, base + (size_t)n * HIDDEN + o * 8, 16);
    }
    cpasync_commit();
}

__global__ void __launch_bounds__(512, 1) k_gru_fused(
    int layer, const float* __restrict__ bih, const float* __restrict__ bhh)
{
    extern __shared__ uint32_t dsm[];
    const __nv_bfloat16* wcomb = d_Wcomb_bf + (size_t)layer * 3 * HIDDEN * HIDDEN;
    const uint32_t sb = smem_u32(dsm);
    const uint32_t sbB = sb + AS_W * 4;

    const int tid = threadIdx.x, lane = tid & 31, w = tid >> 5;
    const int wm = w & 3, wn = w >> 2;  // 4 m-strips x 4 n-strips
    const int gid = lane >> 2, tg = lane & 3;
    const int row0 = blockIdx.x * 64;
    const int lr1 = wm * 16 + gid, lr2 = lr1 + 8;

    // ---- prologue: async-stage A tile ([agg_bf | h_bf], 64x256 halves) + chunks 0,1 ----
#pragma unroll
    for (int q = tid; q < 2048; q += 512) {
        int r = q >> 5, o = q & 31;  // 32 x 16B per row (16 agg + 16 h)
        int gr = row0 + r;
        int ok = (gr < N_NODES);
        if (!ok) gr = 0;
        const __nv_bfloat16* src = (o < 16) ? d_agg_bf + (size_t)gr * HIDDEN + o * 8
                                            : d_h_bf + (size_t)gr * HIDDEN + (o - 16) * 8;
        cpasync16(sb + (r * S2A + o * 4) * 4, src, ok ? 16 : 0);
    }
    cpasync_commit();
    gru_issueB(sbB, wcomb, 0, tid);
    gru_issueB(sbB + BS_W * 4, wcomb, 1, tid);

    float rr[4][4], nn[4][4], ci[4][4], ch[4][4];
#pragma unroll
    for (int j = 0; j < 4; j++)
#pragma unroll
        for (int q = 0; q < 4; q++) { ci[j][q] = 0.f; ch[j][q] = 0.f; }

    for (int it = 0; it < 12; it++) {
        if (it < 11) asm volatile("cp.async.wait_group 1;" ::: "memory");
        else asm volatile("cp.async.wait_group 0;" ::: "memory");
        __syncthreads();

        if (it + 2 < 12) gru_issueB(sbB + ((it + 2) % 3) * BS_W * 4, wcomb, it + 2, tid);

        const uint32_t* BS = dsm + AS_W + (it % 3) * BS_W;
        const int pass = it >> 2, sub = it & 3;
        float(*acc)[4] = (pass == 1 && sub >= 2) ? ch : ci;
        const int kbase = sub * 32;  // half2 units
#pragma unroll
        for (int ks = 0; ks < 4; ks++) {
            int kb = kbase + ks * 8;
            uint32_t af[4];
            af[0] = dsm[lr1 * S2A + kb + tg];
            af[1] = dsm[lr2 * S2A + kb + tg];
            af[2] = dsm[lr1 * S2A + kb + tg + 4];
            af[3] = dsm[lr2 * S2A + kb + tg + 4];
#pragma unroll
            for (int nt = 0; nt < 4; nt++) {
                uint32_t bf[2];
                int nb = wn * 32 + nt * 8 + gid;
                bf[0] = BS[nb * S2B + ks * 8 + tg];
                bf[1] = BS[nb * S2B + ks * 8 + tg + 4];
                mma_bf16(acc[nt], af, bf);
            }
        }

        if (sub == 3) {
            if (pass == 0) {  // R
#pragma unroll
                for (int nt = 0; nt < 4; nt++) {
                    int coli = wn * 32 + nt * 8 + tg * 2;
                    float b0 = bih[coli] + bhh[coli];
                    float b1 = bih[coli + 1] + bhh[coli + 1];
                    rr[nt][0] = sigm_f(ci[nt][0] + b0);
                    rr[nt][1] = sigm_f(ci[nt][1] + b1);
                    rr[nt][2] = sigm_f(ci[nt][2] + b0);
                    rr[nt][3] = sigm_f(ci[nt][3] + b1);
#pragma unroll
                    for (int q = 0; q < 4; q++) ci[nt][q] = 0.f;
                }
            } else if (pass == 1) {  // N
#pragma unroll
                for (int nt = 0; nt < 4; nt++) {
                    int coli = wn * 32 + nt * 8 + tg * 2;
                    float bi0 = bih[256 + coli], bi1 = bih[256 + coli + 1];
                    float bh0 = bhh[256 + coli], bh1 = bhh[256 + coli + 1];
                    nn[nt][0] = tanh_f(ci[nt][0] + bi0 + rr[nt][0] * (ch[nt][0] + bh0));
                    nn[nt][1] = tanh_f(ci[nt][1] + bi1 + rr[nt][1] * (ch[nt][1] + bh1));
                    nn[nt][2] = tanh_f(ci[nt][2] + bi0 + rr[nt][2] * (ch[nt][2] + bh0));
                    nn[nt][3] = tanh_f(ci[nt][3] + bi1 + rr[nt][3] * (ch[nt][3] + bh1));
#pragma unroll
                    for (int q = 0; q < 4; q++) ci[nt][q] = 0.f;
                }
            } else {  // Z + in-place h update (fp32 + bf16 mirror)
                int gr1 = row0 + lr1, gr2 = row0 + lr2;
#pragma unroll
                for (int nt = 0; nt < 4; nt++) {
                    int coli = wn * 32 + nt * 8 + tg * 2;
                    float b0 = bih[128 + coli] + bhh[128 + coli];
                    float b1 = bih[128 + coli + 1] + bhh[128 + coli + 1];
                    if (gr1 < N_NODES) {
                        float* hp = d_h + (size_t)gr1 * HIDDEN + coli;
                        float2 h = *(float2*)hp;
                        float z0 = sigm_f(ci[nt][0] + b0), z1 = sigm_f(ci[nt][1] + b1);
                        float2 o;
                        o.x = (1.f - z0) * nn[nt][0] + z0 * h.x;
                        o.y = (1.f - z1) * nn[nt][1] + z1 * h.y;
                        *(float2*)hp = o;
                        ((uint32_t*)d_h_bf)[((size_t)gr1 * HIDDEN + coli) >> 1] = bf2(o.x, o.y);
                    }
                    if (gr2 < N_NODES) {
                        float* hp = d_h + (size_t)gr2 * HIDDEN + coli;
                        float2 h = *(float2*)hp;
                        float z0 = sigm_f(ci[nt][2] + b0), z1 = sigm_f(ci[nt][3] + b1);
                        float2 o;
                        o.x = (1.f - z0) * nn[nt][2] + z0 * h.x;
                        o.y = (1.f - z1) * nn[nt][3] + z1 * h.y;
                        *(float2*)hp = o;
                        ((uint32_t*)d_h_bf)[((size_t)gr2 * HIDDEN + coli) >> 1] = bf2(o.x, o.y);
                    }
                }
            }
        }
    }
}

// ---------------- Wcomb precompute: bf16( wih[g*128+n][:] . ggnn[l][k][:] ) ----------------
__global__ void __launch_bounds__(256) k_wcomb(const float* __restrict__ wih,
                                               const float* __restrict__ ggnn) {
    __shared__ float As[16][128];
    __shared__ float Bs[16][128];
    const float* A = wih + (size_t)blockIdx.x * 128 * HIDDEN;
    const float* B = ggnn + (size_t)blockIdx.y * HIDDEN * HIDDEN;
    __nv_bfloat16* C = d_Wcomb_bf + ((size_t)blockIdx.y * 3 + blockIdx.x) * 128 * HIDDEN;
    const int tid = threadIdx.x, tx = tid & 15, ty = tid >> 4;

    float acc[8][8];
#pragma unroll
    for (int i = 0; i < 8; i++)
#pragma unroll
        for (int j = 0; j < 8; j++) acc[i][j] = 0.f;

    for (int j0 = 0; j0 < 128; j0 += 16) {
#pragma unroll
        for (int q = tid; q < 512; q += 256) {
            int n = q >> 2, j4 = (q & 3) << 2;
            float4 va = *(const float4*)(A + (size_t)n * HIDDEN + j0 + j4);
            As[j4 + 0][n] = va.x; As[j4 + 1][n] = va.y;
            As[j4 + 2][n] = va.z; As[j4 + 3][n] = va.w;
            float4 vb = *(const float4*)(B + (size_t)n * HIDDEN + j0 + j4);
            Bs[j4 + 0][n] = vb.x; Bs[j4 + 1][n] = vb.y;
            Bs[j4 + 2][n] = vb.z; Bs[j4 + 3][n] = vb.w;
        }
        __syncthreads();
#pragma unroll
        for (int jj = 0; jj < 16; jj++) {
            float a[8], b[8];
#pragma unroll
            for (int i = 0; i < 8; i++) a[i] = As[jj][ty * 8 + i];
#pragma unroll
            for (int j = 0; j < 8; j++) b[j] = Bs[jj][tx * 8 + j];
#pragma unroll
            for (int i = 0; i < 8; i++)
#pragma unroll
                for (int j = 0; j < 8; j++) acc[i][j] = fmaf(a[i], b[j], acc[i][j]);
        }
        __syncthreads();
    }
#pragma unroll
    for (int i = 0; i < 8; i++)
#pragma unroll
        for (int j = 0; j < 8; j++)
            C[(size_t)(ty * 8 + i) * HIDDEN + tx * 8 + j] = __float2bfloat16(acc[i][j]);
}

__global__ void k_whh_bf(const float* __restrict__ whh) {
    int i = blockIdx.x * blockDim.x + threadIdx.x;  // < 49152
    d_whh_bf[i] = __float2bfloat16(whh[i]);
}

// ---------------- HMMA tf32 GEMM tile (fc1), 256 thr, occ 2 ----------------
template <bool HASBIAS>
__device__ __forceinline__ void hmma_tile(
    const float* __restrict__ A, const float* __restrict__ Bt,
    const float* __restrict__ bias, float* __restrict__ C, int ldc, int ccol0)
{
    __shared__ uint32_t As[128 * ASTRIDE];
    __shared__ uint32_t Bs[128 * ASTRIDE];
    const int tid = threadIdx.x, lane = tid & 31, w = tid >> 5;
    const int wm = w & 3, wn = w >> 2;
    const int gid = lane >> 2, tg = lane & 3;
    const int row0 = blockIdx.x * 128;

    float c[2][8][4];
#pragma unroll
    for (int i = 0; i < 2; i++)
#pragma unroll
        for (int j = 0; j < 8; j++)
#pragma unroll
            for (int q = 0; q < 4; q++) c[i][j][q] = 0.f;

#pragma unroll
    for (int kp = 0; kp < 4; kp++) {
        if (kp) __syncthreads();
#pragma unroll
        for (int q = tid; q < 1024; q += 256) {
            int r = q >> 3, k4 = (q & 7) << 2;
            int gr = row0 + r;
            if (gr >= N_NODES) gr = N_NODES - 1;
            float4 va = *(const float4*)(A + (size_t)gr * HIDDEN + kp * 32 + k4);
            *(uint4*)(As + r * ASTRIDE + k4) =
                make_uint4(f2tf32(va.x), f2tf32(va.y), f2tf32(va.z), f2tf32(va.w));
            float4 vb = *(const float4*)(Bt + (size_t)r * HIDDEN + kp * 32 + k4);
            *(uint4*)(Bs + r * ASTRIDE + k4) =
                make_uint4(f2tf32(vb.x), f2tf32(vb.y), f2tf32(vb.z), f2tf32(vb.w));
        }
        __syncthreads();
#pragma unroll
        for (int ks = 0; ks < 4; ks++) {
            int k0 = ks * 8;
            uint32_t af[2][4];
#pragma unroll
            for (int mt = 0; mt < 2; mt++) {
                int rb = wm * 32 + mt * 16;
                af[mt][0] = As[(rb + gid) * ASTRIDE + k0 + tg];
                af[mt][1] = As[(rb + gid + 8) * ASTRIDE + k0 + tg];
                af[mt][2] = As[(rb + gid) * ASTRIDE + k0 + tg + 4];
                af[mt][3] = As[(rb + gid + 8) * ASTRIDE + k0 + tg + 4];
            }
#pragma unroll
            for (int nt = 0; nt < 8; nt++) {
                uint32_t bf[2];
                int nb = wn * 64 + nt * 8 + gid;
                bf[0] = Bs[nb * ASTRIDE + k0 + tg];
                bf[1] = Bs[nb * ASTRIDE + k0 + tg + 4];
#pragma unroll
                for (int mt = 0; mt < 2; mt++) mma_tf32(c[mt][nt], af[mt], bf);
            }
        }
    }

#pragma unroll
    for (int mt = 0; mt < 2; mt++) {
        int r1 = row0 + wm * 32 + mt * 16 + gid;
        int r2 = r1 + 8;
#pragma unroll
        for (int nt = 0; nt < 8; nt++) {
            int coli = wn * 64 + nt * 8 + tg * 2;
            float b0 = 0.f, b1 = 0.f;
            if (HASBIAS) { b0 = bias[coli]; b1 = bias[coli + 1]; }
            if (r1 < N_NODES) {
                float2 v = make_float2(c[mt][nt][0] + b0, c[mt][nt][1] + b1);
                *(float2*)(C + (size_t)r1 * ldc + ccol0 + coli) = v;
            }
            if (r2 < N_NODES) {
                float2 v = make_float2(c[mt][nt][2] + b0, c[mt][nt][3] + b1);
                *(float2*)(C + (size_t)r2 * ldc + ccol0 + coli) = v;
            }
        }
    }
}

__global__ void __launch_bounds__(256, 2) k_mma_fc1(
    const float* __restrict__ w, const float* __restrict__ b) {
    hmma_tile<true>(d_h, w, b, d_m, HIDDEN, 0);
}

// ---------------- setup kernels ----------------
__global__ void k_init() {
    int i = blockIdx.x * blockDim.x + threadIdx.x;
    if (i < N_NODES) d_deg[i] = 0;
    if (i < NUM_GRAPHS * HIDDEN) d_pool[i] = 0.f;
    if (i < NUM_GRAPHS) d_cnt[i] = 0;
    if (i < HIDDEN) { d_sum[i] = 0.f; d_sumsq[i] = 0.f; }
}

__global__ void k_copy_x(const float* __restrict__ x) {
    int i = blockIdx.x * blockDim.x + threadIdx.x;  // 3.2M float4
    float4 v = ((const float4*)x)[i];
    ((float4*)d_h)[i] = v;
    ((uint2*)d_h_bf)[i] = make_uint2(bf2(v.x, v.y), bf2(v.z, v.w));
}

__global__ void k_edges(const int* __restrict__ e) {
    int i = blockIdx.x * blockDim.x + threadIdx.x;
    int s = e[i];
    int d = e[N_EDGES + i];
    d_src[i] = s;
    d_dst[i] = d;
    atomicAdd(&d_deg[d], 1);
}

__global__ void k_batch_hist(const int* __restrict__ batch) {
    __shared__ int hc[NUM_GRAPHS];
    for (int i = threadIdx.x; i < NUM_GRAPHS; i += blockDim.x) hc[i] = 0;
    __syncthreads();
    int idx = blockIdx.x * blockDim.x + threadIdx.x;
    if (idx < N_NODES) atomicAdd(&hc[batch[idx]], 1);
    __syncthreads();
    for (int i = threadIdx.x; i < NUM_GRAPHS; i += blockDim.x)
        if (hc[i]) atomicAdd(&d_cnt[i], hc[i]);
}

__global__ void k_scan1() {
    __shared__ int sh[32];
    int lane = threadIdx.x & 31, warp = threadIdx.x >> 5;
    int idx = blockIdx.x * 1024 + threadIdx.x;
    int v = (idx < N_NODES) ? d_deg[idx] : 0;
#pragma unroll
    for (int o = 16; o; o >>= 1) v += __shfl_down_sync(0xFFFFFFFFu, v, o);
    if (lane == 0) sh[warp] = v;
    __syncthreads();
    if (warp == 0) {
        v = sh[lane];
#pragma unroll
        for (int o = 16; o; o >>= 1) v += __shfl_down_sync(0xFFFFFFFFu, v, o);
        if (lane == 0) d_blocksum[blockIdx.x] = v;
    }
}

__global__ void k_scan2() {
    __shared__ int s[128];
    int t = threadIdx.x;
    int v = (t < 98) ? d_blocksum[t] : 0;
    s[t] = v;
    __syncthreads();
#pragma unroll
    for (int o = 1; o < 128; o <<= 1) {
        int tmp = (t >= o) ? s[t - o] : 0;
        __syncthreads();
        s[t] += tmp;
        __syncthreads();
    }
    if (t < 98) d_blockoff[t] = s[t] - v;
    if (t == 0) d_rowptr[N_NODES] = s[97];
}

__global__ void k_scan3() {
    __shared__ int s[1024];
    int t = threadIdx.x;
    int idx = blockIdx.x * 1024 + t;
    int v = (idx < N_NODES) ? d_deg[idx] : 0;
    s[t] = v;
    __syncthreads();
#pragma unroll
    for (int o = 1; o < 1024; o <<= 1) {
        int tmp = (t >= o) ? s[t - o] : 0;
        __syncthreads();
        s[t] += tmp;
        __syncthreads();
    }
    if (idx < N_NODES) {
        int ex = d_blockoff[blockIdx.x] + s[t] - v;
        d_rowptr[idx] = ex;
        d_cursor[idx] = ex;
    }
}

__global__ void k_csr_fill() {
    int i = blockIdx.x * blockDim.x + threadIdx.x;
    int pos = atomicAdd(&d_cursor[d_dst[i]], 1);
    d_colidx[pos] = d_src[i];
}

// ---------------- CSR aggregate of h (bf16): one warp per destination node ----------------
__global__ void k_aggregate() {
    int warp = (blockIdx.x * blockDim.x + threadIdx.x) >> 5;
    int lane = threadIdx.x & 31;
    if (warp >= N_NODES) return;
    int beg = d_rowptr[warp], end = d_rowptr[warp + 1];
    const uint2* hb = (const uint2*)d_h_bf;  // 32 uint2 per row
    float4 acc = make_float4(0.f, 0.f, 0.f, 0.f);
    for (int e = beg; e < end; e++) {
        int src = d_colidx[e];
        uint2 v = hb[(size_t)src * 32 + lane];
        float2 f0 = __bfloat1622float2(*(__nv_bfloat162*)&v.x);
        float2 f1 = __bfloat1622float2(*(__nv_bfloat162*)&v.y);
        acc.x += f0.x; acc.y += f0.y; acc.z += f1.x; acc.w += f1.y;
    }
    ((uint2*)d_agg_bf)[(size_t)warp * 32 + lane] =
        make_uint2(bf2(acc.x, acc.y), bf2(acc.z, acc.w));
}

// ---------------- batchnorm + relu + mean pool + classifier ----------------
__global__ void k_bn_stats() {
    int c = threadIdx.x;
    int n0 = blockIdx.x * 500;
    int n1 = n0 + 500;
    float s = 0.f, s2 = 0.f;
    for (int n = n0; n < n1; n++) {
        float v = d_m[(size_t)n * HIDDEN + c];
        s += v;
        s2 += v * v;
    }
    atomicAdd(&d_sum[c], s);
    atomicAdd(&d_sumsq[c], s2);
}

__global__ void k_bn_final() {
    int c = threadIdx.x;
    float mu = d_sum[c] / (float)N_NODES;
    float var = d_sumsq[c] / (float)N_NODES - mu * mu;
    d_mean[c] = mu;
    d_rstd[c] = rsqrtf(var + BN_EPS);
}

__global__ void k_pool(const int* __restrict__ batch,
                       const float* __restrict__ gamma,
                       const float* __restrict__ beta) {
    int c = threadIdx.x;
    int n0 = blockIdx.x * 512;
    int n1 = n0 + 512;
    if (n1 > N_NODES) n1 = N_NODES;
    if (n0 >= N_NODES) return;
    float sc = gamma[c] * d_rstd[c];
    float mu = d_mean[c];
    float be = beta[c];
    float acc = 0.f;
    int cur = batch[n0];
    for (int n = n0; n < n1; n++) {
        int bb = batch[n];
        if (bb != cur) {
            atomicAdd(&d_pool[cur * HIDDEN + c], acc);
            acc = 0.f;
            cur = bb;
        }
        float v = (d_m[(size_t)n * HIDDEN + c] - mu) * sc + be;
        acc += fmaxf(v, 0.f);
    }
    atomicAdd(&d_pool[cur * HIDDEN + c], acc);
}

__global__ void k_final(const float* __restrict__ w2, const float* __restrict__ b2,
                        float* __restrict__ out) {
    __shared__ float sf[HIDDEN];
    __shared__ float lg[NUM_CLASSES];
    int g = blockIdx.x, t = threadIdx.x;
    float cnt = fmaxf((float)d_cnt[g], 1.f);
    sf[t] = d_pool[g * HIDDEN + t] / cnt;
    __syncthreads();
    if (t < NUM_CLASSES) {
        float s = b2[t];
        for (int k = 0; k < HIDDEN; k++) s += sf[k] * w2[t * HIDDEN + k];
        lg[t] = s;
    }
    __syncthreads();
    if (t == 0) {
        float mx = -1e30f;
        for (int c = 0; c < NUM_CLASSES; c++) mx = fmaxf(mx, lg[c]);
        float se = 0.f;
        for (int c = 0; c < NUM_CLASSES; c++) se += expf(lg[c] - mx);
        float lse = mx + logf(se);
        for (int c = 0; c < NUM_CLASSES; c++) out[g * NUM_CLASSES + c] = lg[c] - lse;
    }
}

// ---------------- launch ----------------
extern "C" void kernel_launch(void* const* d_in, const int* in_sizes, int n_in,
                              void* d_out, int out_size) {
    const float* x     = (const float*)d_in[0];
    const int*   ei    = (const int*)d_in[1];
    const int*   bat   = (const int*)d_in[2];
    const float* ggnn  = (const float*)d_in[3];
    const float* wih   = (const float*)d_in[4];
    const float* whh   = (const float*)d_in[5];
    const float* bih   = (const float*)d_in[6];
    const float* bhh   = (const float*)d_in[7];
    const float* fc1w  = (const float*)d_in[8];
    const float* fc1b  = (const float*)d_in[9];
    const float* gamma = (const float*)d_in[10];
    const float* beta  = (const float*)d_in[11];
    const float* fc2w  = (const float*)d_in[12];
    const float* fc2b  = (const float*)d_in[13];
    float* out = (float*)d_out;

    cudaFuncSetAttribute(k_gru_fused, cudaFuncAttributeMaxDynamicSharedMemorySize,
                         GRU_SMEM_BYTES);

    k_init<<<(N_NODES + 255) / 256, 256>>>();
    k_copy_x<<<(N_NODES * HIDDEN / 4) / 256, 256>>>(x);
    k_edges<<<N_EDGES / 256, 256>>>(ei);
    k_batch_hist<<<98, 1024>>>(bat);
    k_scan1<<<98, 1024>>>();
    k_scan2<<<1, 128>>>();
    k_scan3<<<98, 1024>>>();
    k_csr_fill<<<N_EDGES / 256, 256>>>();
    k_wcomb<<<dim3(3, NUM_LAYERS), 256>>>(wih, ggnn);
    k_whh_bf<<<192, 256>>>(whh);

    const int gru_blocks = (N_NODES + 63) / 64;  // 1563
    for (int l = 0; l < NUM_LAYERS; l++) {
        k_aggregate<<<(N_NODES * 32) / 256, 256>>>();
        k_gru_fused<<<gru_blocks, 512, GRU_SMEM_BYTES>>>(l, bih, bhh);
    }

    k_mma_fc1<<<(N_NODES + 127) / 128, 256>>>(fc1w, fc1b);
    k_bn_stats<<<200, 128>>>();
    k_bn_final<<<1, 128>>>();
    k_pool<<<(N_NODES + 511) / 512, 128>>>(bat, gamma, beta);
    k_final<<<NUM_GRAPHS, 128>>>(fc2w, fc2b, out);
}